// round 11
// baseline (speedup 1.0000x reference)
#include <cuda_runtime.h>
#include <cuda_bf16.h>
#include <math.h>
#include <stdint.h>

#define NMAX 50048
#define EMAX 1000000
#define F 128
#define LN_EPS 1e-5f

// ---------------------------------------------------------------------------
// Scratch (device globals — no allocation allowed)
__device__ float g_XA[NMAX * F];
__device__ float g_XB[NMAX * F];
__device__ float g_AGGS[NMAX * F];
__device__ float g_DELTA[NMAX * 3];
__device__ float g_DEG[NMAX];
__device__ float g_V[F];
__device__ float g_C0;
__device__ int   g_IS64;
__device__ int   g_CNT[NMAX];
__device__ int   g_RUN[NMAX];
__device__ int2  g_SRC[EMAX];     // sorted (row, col) pairs

// ---------------------------------------------------------------------------
#define FFMA2(acc, a, b) \
    asm("fma.rn.f32x2 %0, %1, %2, %0;" : "+l"(acc) : "l"(a), "l"(b))
__device__ __forceinline__ unsigned long long pack2(float v) {
    unsigned long long r;
    unsigned int u = __float_as_uint(v);
    asm("mov.b64 %0, {%1, %1};" : "=l"(r) : "r"(u));
    return r;
}
__device__ __forceinline__ void unpack2(unsigned long long p, float& lo, float& hi) {
    unsigned int a, b;
    asm("mov.b64 {%0, %1}, %2;" : "=r"(a), "=r"(b) : "l"(p));
    lo = __uint_as_float(a);
    hi = __uint_as_float(b);
}
__device__ __forceinline__ uint32_t smem_u32(const void* p) {
    uint32_t a;
    asm("{ .reg .u64 t; cvta.to.shared.u64 t, %1; cvt.u32.u64 %0, t; }"
        : "=r"(a) : "l"(p));
    return a;
}
#define CP_ASYNC16(dst, src) \
    asm volatile("cp.async.cg.shared.global [%0], [%1], 16;" :: "r"(dst), "l"(src))
#define CP_COMMIT() asm volatile("cp.async.commit_group;" ::: "memory")
#define CP_WAIT0()  asm volatile("cp.async.wait_group 0;" ::: "memory")

__device__ __forceinline__ float fast_sigmoid(float p) {
    return __fdividef(1.f, 1.f + __expf(-p));
}
__device__ __forceinline__ float fast_tanh(float x) {
    return 1.f - __fdividef(2.f, __expf(2.f * x) + 1.f);
}

// ---------------------------------------------------------------------------
__global__ void detect_kernel(const void* ei, int E, int N) {
    __shared__ int bad;
    if (threadIdx.x == 0) bad = 0;
    __syncthreads();
    int cnt = (2 * E < 256) ? 2 * E : 256;
    if ((int)threadIdx.x < cnt) {
        long long v = ((const long long*)ei)[threadIdx.x];
        if (v < 0 || v >= N) bad = 1;
    }
    __syncthreads();
    if (threadIdx.x == 0) g_IS64 = !bad;
}

__global__ void prep_vc(const float* __restrict__ ew2, const float* __restrict__ cw,
                        const float* __restrict__ eb2, const float* __restrict__ cb) {
    int t = threadIdx.x;
    float s = 0.f;
    for (int o = 0; o < F; o++) s += ew2[t * F + o] * cw[o];
    g_V[t] = s;
    if (t == 0) {
        float c = cb[0];
        for (int o = 0; o < F; o++) c += eb2[o] * cw[o];
        g_C0 = c;
    }
}

__global__ void zero_kernel(int N) {
    int n4 = N * 32;
    float4 z4 = make_float4(0.f, 0.f, 0.f, 0.f);
    float4* a4 = (float4*)g_AGGS;
    int stride = gridDim.x * blockDim.x;
    for (int i = blockIdx.x * blockDim.x + threadIdx.x; i < n4; i += stride) a4[i] = z4;
    for (int i = blockIdx.x * blockDim.x + threadIdx.x; i < N * 3; i += stride) g_DELTA[i] = 0.f;
}

// ---------------------------------------------------------------------------
// CSR-style sort by destination row
__global__ void zero_cnt(int N) {
    int i = blockIdx.x * blockDim.x + threadIdx.x;
    if (i < N) g_CNT[i] = 0;
}

__global__ void hist_kernel(const void* __restrict__ ei_raw, int E) {
    int i = blockIdx.x * blockDim.x + threadIdx.x;
    if (i >= E) return;
    int row = g_IS64 ? (int)((const long long*)ei_raw)[i] : ((const int*)ei_raw)[i];
    atomicAdd(&g_CNT[row], 1);
}

// exclusive scan; also emits DEG (degree as float)
__global__ void scan_kernel(int N) {
    __shared__ int part[1024];
    int tid = threadIdx.x;
    int chunk = (N + 1023) / 1024;
    int lo = tid * chunk;
    int hi = lo + chunk < N ? lo + chunk : N;
    int s = 0;
    for (int i = lo; i < hi; i++) s += g_CNT[i];
    part[tid] = s;
    __syncthreads();
    for (int o = 1; o < 1024; o <<= 1) {
        int u = (tid >= o) ? part[tid - o] : 0;
        __syncthreads();
        part[tid] += u;
        __syncthreads();
    }
    int run = (tid == 0) ? 0 : part[tid - 1];
    for (int i = lo; i < hi; i++) {
        g_RUN[i] = run;
        g_DEG[i] = (float)g_CNT[i];
        run += g_CNT[i];
    }
}

__global__ void scatter_kernel(const void* __restrict__ ei_raw, int E) {
    int i = blockIdx.x * blockDim.x + threadIdx.x;
    if (i >= E) return;
    int row, col;
    if (g_IS64) {
        const long long* ei = (const long long*)ei_raw;
        row = (int)ei[i];
        col = (int)ei[(size_t)E + i];
    } else {
        const int* ei = (const int*)ei_raw;
        row = ei[i];
        col = ei[E + i];
    }
    int p = atomicAdd(&g_RUN[row], 1);
    g_SRC[p] = make_int2(row, col);
}

// ---------------------------------------------------------------------------
// Sorted-edge kernel: one warp per 8 consecutive sorted edges.
// Same-row runs share one RED flush; XA/pos[row] are L1-hot within the run.
__global__ void __launch_bounds__(256)
edge_sorted(const float* __restrict__ pos, const float* __restrict__ ew1, int E) {
    int g = (blockIdx.x * blockDim.x + threadIdx.x) >> 5;
    int lane = threadIdx.x & 31;
    int i0 = g * 8;
    if (i0 >= E) return;

    int2 rc = make_int2(-1, -1);
    if (lane < 8 && i0 + lane < E) rc = g_SRC[i0 + lane];
    int rows[8], cols[8];
#pragma unroll
    for (int j = 0; j < 8; j++) {
        rows[j] = __shfl_sync(0xffffffffu, rc.x, j);
        cols[j] = __shfl_sync(0xffffffffu, rc.y, j);
    }

    float4 w  = __ldg((const float4*)(ew1 + 256 * F) + lane);
    float4 vv = ((const float4*)g_V)[lane];
    float c0 = g_C0;

    const float4* XA4 = (const float4*)g_XA;
    const float4* XB4 = (const float4*)g_XB;

    float4 s[8];
    float df[8], cdx[8], cdy[8], cdz[8];
#pragma unroll
    for (int j = 0; j < 8; j++) {
        s[j] = make_float4(0.f, 0.f, 0.f, 0.f);
        df[j] = 0.f; cdx[j] = 0.f; cdy[j] = 0.f; cdz[j] = 0.f;
        int r = rows[j], c = cols[j];
        if (r >= 0) {
            float4 xa = XA4[(size_t)r * 32 + lane];   // L1-hot within same-row run
            float4 xb = XB4[(size_t)c * 32 + lane];
            float dx = __ldg(&pos[r * 3 + 0]) - __ldg(&pos[c * 3 + 0]);
            float dy = __ldg(&pos[r * 3 + 1]) - __ldg(&pos[c * 3 + 1]);
            float dz = __ldg(&pos[r * 3 + 2]) - __ldg(&pos[c * 3 + 2]);
            float d2 = dx * dx + dy * dy + dz * dz;

            float p0 = xa.x + xb.x + d2 * w.x;
            float p1 = xa.y + xb.y + d2 * w.y;
            float p2 = xa.z + xb.z + d2 * w.z;
            float p3 = xa.w + xb.w + d2 * w.w;

            float s0 = p0 * fast_sigmoid(p0);
            float s1 = p1 * fast_sigmoid(p1);
            float s2 = p2 * fast_sigmoid(p2);
            float s3 = p3 * fast_sigmoid(p3);

            s[j] = make_float4(s0, s1, s2, s3);
            df[j] = s0 * vv.x + s1 * vv.y + s2 * vv.z + s3 * vv.w;
            cdx[j] = dx; cdy[j] = dy; cdz[j] = dz;
        }
    }

    // 8 interleaved butterflies (40 independent SHFLs, pipelined)
#pragma unroll
    for (int o = 16; o > 0; o >>= 1) {
#pragma unroll
        for (int j = 0; j < 8; j++)
            df[j] += __shfl_xor_sync(0xffffffffu, df[j], o);
    }
#pragma unroll
    for (int j = 0; j < 8; j++) {
        float sc = (rows[j] >= 0) ? fast_tanh(df[j] + c0) : 0.f;
        cdx[j] *= sc; cdy[j] *= sc; cdz[j] *= sc;
    }

    // Flush same-row runs with a single RED each
    int cur = rows[0];
    float4 acc = s[0];
    float ax = cdx[0], ay = cdy[0], az = cdz[0];
#pragma unroll
    for (int j = 1; j < 8; j++) {
        if (rows[j] == cur) {
            acc.x += s[j].x; acc.y += s[j].y; acc.z += s[j].z; acc.w += s[j].w;
            ax += cdx[j]; ay += cdy[j]; az += cdz[j];
        } else {
            if (cur >= 0) {
                float* aggp = g_AGGS + (size_t)cur * F + lane * 4;
                asm volatile("red.global.add.v4.f32 [%0], {%1, %2, %3, %4};"
                             :: "l"(aggp), "f"(acc.x), "f"(acc.y), "f"(acc.z), "f"(acc.w)
                             : "memory");
                if (lane == 0) {
                    atomicAdd(&g_DELTA[cur * 3 + 0], ax);
                    atomicAdd(&g_DELTA[cur * 3 + 1], ay);
                    atomicAdd(&g_DELTA[cur * 3 + 2], az);
                }
            }
            cur = rows[j];
            acc = s[j];
            ax = cdx[j]; ay = cdy[j]; az = cdz[j];
        }
    }
    if (cur >= 0) {
        float* aggp = g_AGGS + (size_t)cur * F + lane * 4;
        asm volatile("red.global.add.v4.f32 [%0], {%1, %2, %3, %4};"
                     :: "l"(aggp), "f"(acc.x), "f"(acc.y), "f"(acc.z), "f"(acc.w)
                     : "memory");
        if (lane == 0) {
            atomicAdd(&g_DELTA[cur * 3 + 0], ax);
            atomicAdd(&g_DELTA[cur * 3 + 1], ay);
            atomicAdd(&g_DELTA[cur * 3 + 2], az);
        }
    }
}

// ---------------------------------------------------------------------------
// Pipelined register-tiled GEMM (unchanged from R10)
#define AS_STRIDE 132
#define WS_BYTES  16384
#define AS_BYTES  16896
#define SM_AS0    (2 * WS_BYTES)
#define SM_RT_TOTAL (2 * WS_BYTES + 2 * AS_BYTES)

template <int ACT>
__global__ void __launch_bounds__(256, 2)
gemm_rt(const float* __restrict__ A,
        const float* __restrict__ W0, const float* __restrict__ bias0,
        float* __restrict__ out0,
        const float* __restrict__ W1, const float* __restrict__ bias1,
        float* __restrict__ out1,
        const float* __restrict__ deg, const float* __restrict__ degvec, int N) {
    extern __shared__ char smem[];

    const float* W = W0;
    const float* bias = bias0;
    float* out = out0;
    if (blockIdx.y == 1) { W = W1; bias = bias1; out = out1; }

    int t = threadIdx.x;
    int lane = t & 31, w = t >> 5;
    int txl = lane & 3, tyl = lane >> 2;
    int wx = w & 3, wy = w >> 2;
    int col0 = (wx * 4 + txl) * 8;
    int rowt = (wy * 8 + tyl) * 8;
    int row0 = blockIdx.x * 128;

    uint32_t sb = smem_u32(smem);

    int arl = (w & 3) * 32 + lane;
    int kh  = (w >> 2) * 16;
    int arow = row0 + arl;
    const float4* Abase = (const float4*)(A + (size_t)arow * F);

    int wk = t >> 3, wcol = (t & 7) * 16;

    unsigned long long acc[8][4];
#pragma unroll
    for (int r = 0; r < 8; r++)
#pragma unroll
        for (int c = 0; c < 4; c++) acc[r][c] = 0ull;

    float4 v[4];

    {
        const float* wsrc = W + (size_t)wk * F + wcol;
        uint32_t wdst = sb + (uint32_t)(wk * F + wcol) * 4;
#pragma unroll
        for (int q = 0; q < 4; q++) CP_ASYNC16(wdst + q * 16, wsrc + q * 4);
        CP_COMMIT();
        if (arow < N) {
#pragma unroll
            for (int q = 0; q < 4; q++) v[q] = __ldg(&Abase[(kh >> 2) + q]);
        } else {
#pragma unroll
            for (int q = 0; q < 4; q++) v[q] = make_float4(0.f, 0.f, 0.f, 0.f);
        }
        float* As0 = (float*)(smem + SM_AS0);
#pragma unroll
        for (int q = 0; q < 4; q++) {
            float vals[4] = {v[q].x, v[q].y, v[q].z, v[q].w};
#pragma unroll
            for (int e = 0; e < 4; e++)
                As0[(kh + q * 4 + e) * AS_STRIDE + arl] = vals[e];
        }
        CP_WAIT0();
    }
    __syncthreads();

#pragma unroll 1
    for (int c = 0; c < 4; c++) {
        int cb = c & 1, nb = (c + 1) & 1;
        float* Ws = (float*)(smem + cb * WS_BYTES);
        float* As = (float*)(smem + SM_AS0 + cb * AS_BYTES);

        if (c < 3) {
            const float* wsrc = W + (size_t)((c + 1) * 32 + wk) * F + wcol;
            uint32_t wdst = sb + (uint32_t)nb * WS_BYTES + (uint32_t)(wk * F + wcol) * 4;
#pragma unroll
            for (int q = 0; q < 4; q++) CP_ASYNC16(wdst + q * 16, wsrc + q * 4);
            CP_COMMIT();
            if (arow < N) {
                int kb = ((c + 1) * 32 + kh) >> 2;
#pragma unroll
                for (int q = 0; q < 4; q++) v[q] = __ldg(&Abase[kb + q]);
            }
        }

#pragma unroll
        for (int kk = 0; kk < 32; kk++) {
            float4 al = *(const float4*)&As[kk * AS_STRIDE + rowt];
            float4 ah = *(const float4*)&As[kk * AS_STRIDE + rowt + 4];
            unsigned long long a0 = pack2(al.x), a1 = pack2(al.y);
            unsigned long long a2 = pack2(al.z), a3 = pack2(al.w);
            unsigned long long a4 = pack2(ah.x), a5 = pack2(ah.y);
            unsigned long long a6 = pack2(ah.z), a7 = pack2(ah.w);
            ulonglong2 bv0 = *(const ulonglong2*)&Ws[kk * F + col0];
            ulonglong2 bv1 = *(const ulonglong2*)&Ws[kk * F + col0 + 4];
            FFMA2(acc[0][0], a0, bv0.x); FFMA2(acc[0][1], a0, bv0.y);
            FFMA2(acc[0][2], a0, bv1.x); FFMA2(acc[0][3], a0, bv1.y);
            FFMA2(acc[1][0], a1, bv0.x); FFMA2(acc[1][1], a1, bv0.y);
            FFMA2(acc[1][2], a1, bv1.x); FFMA2(acc[1][3], a1, bv1.y);
            FFMA2(acc[2][0], a2, bv0.x); FFMA2(acc[2][1], a2, bv0.y);
            FFMA2(acc[2][2], a2, bv1.x); FFMA2(acc[2][3], a2, bv1.y);
            FFMA2(acc[3][0], a3, bv0.x); FFMA2(acc[3][1], a3, bv0.y);
            FFMA2(acc[3][2], a3, bv1.x); FFMA2(acc[3][3], a3, bv1.y);
            FFMA2(acc[4][0], a4, bv0.x); FFMA2(acc[4][1], a4, bv0.y);
            FFMA2(acc[4][2], a4, bv1.x); FFMA2(acc[4][3], a4, bv1.y);
            FFMA2(acc[5][0], a5, bv0.x); FFMA2(acc[5][1], a5, bv0.y);
            FFMA2(acc[5][2], a5, bv1.x); FFMA2(acc[5][3], a5, bv1.y);
            FFMA2(acc[6][0], a6, bv0.x); FFMA2(acc[6][1], a6, bv0.y);
            FFMA2(acc[6][2], a6, bv1.x); FFMA2(acc[6][3], a6, bv1.y);
            FFMA2(acc[7][0], a7, bv0.x); FFMA2(acc[7][1], a7, bv0.y);
            FFMA2(acc[7][2], a7, bv1.x); FFMA2(acc[7][3], a7, bv1.y);
        }

        if (c < 3) {
            float* Asn = (float*)(smem + SM_AS0 + nb * AS_BYTES);
            if (arow >= N) {
#pragma unroll
                for (int q = 0; q < 4; q++) v[q] = make_float4(0.f, 0.f, 0.f, 0.f);
            }
#pragma unroll
            for (int q = 0; q < 4; q++) {
                float vals[4] = {v[q].x, v[q].y, v[q].z, v[q].w};
#pragma unroll
                for (int e = 0; e < 4; e++)
                    Asn[(kh + q * 4 + e) * AS_STRIDE + arl] = vals[e];
            }
            CP_WAIT0();
        }
        __syncthreads();
    }

    float bcol[8], dcol[8];
#pragma unroll
    for (int j = 0; j < 8; j++) {
        bcol[j] = bias ? __ldg(&bias[col0 + j]) : 0.f;
        dcol[j] = degvec ? __ldg(&degvec[col0 + j]) : 0.f;
    }
#pragma unroll
    for (int rr = 0; rr < 8; rr++) {
        int row = row0 + rowt + rr;
        if (row < N) {
            float dg = deg ? deg[row] : 0.f;
            float o[8];
#pragma unroll
            for (int cp = 0; cp < 4; cp++) unpack2(acc[rr][cp], o[2 * cp], o[2 * cp + 1]);
#pragma unroll
            for (int j = 0; j < 8; j++) {
                float vv2 = o[j] + bcol[j] + dg * dcol[j];
                if (ACT == 1) vv2 = vv2 * fast_sigmoid(vv2);
                o[j] = vv2;
            }
            float4* op = (float4*)(out + (size_t)row * F + col0);
            op[0] = make_float4(o[0], o[1], o[2], o[3]);
            op[1] = make_float4(o[4], o[5], o[6], o[7]);
        }
    }
}

// ---------------------------------------------------------------------------
// Residual + LayerNorm: xout = LN(P + x)
__global__ void __launch_bounds__(256)
ln_kernel(const float* __restrict__ P, const float* __restrict__ x,
          const float* __restrict__ gamma, const float* __restrict__ beta,
          float* __restrict__ xout, int N) {
    int row = blockIdx.x * 8 + (threadIdx.x >> 5);
    int lane = threadIdx.x & 31;
    if (row >= N) return;
    float4 p = ((const float4*)P)[(size_t)row * 32 + lane];
    float4 xv = ((const float4*)x)[(size_t)row * 32 + lane];
    float4 pre = make_float4(p.x + xv.x, p.y + xv.y, p.z + xv.z, p.w + xv.w);
    float s = pre.x + pre.y + pre.z + pre.w;
    float s2 = pre.x * pre.x + pre.y * pre.y + pre.z * pre.z + pre.w * pre.w;
#pragma unroll
    for (int o = 16; o > 0; o >>= 1) {
        s  += __shfl_xor_sync(0xffffffffu, s, o);
        s2 += __shfl_xor_sync(0xffffffffu, s2, o);
    }
    float mean = s * (1.f / F);
    float ri = rsqrtf(s2 * (1.f / F) - mean * mean + LN_EPS);
    float4 g = ((const float4*)gamma)[lane];
    float4 b = ((const float4*)beta)[lane];
    float4 o;
    o.x = g.x * (pre.x - mean) * ri + b.x;
    o.y = g.y * (pre.y - mean) * ri + b.y;
    o.z = g.z * (pre.z - mean) * ri + b.z;
    o.w = g.w * (pre.w - mean) * ri + b.w;
    ((float4*)xout)[(size_t)row * 32 + lane] = o;
}

__global__ void pos_kernel(const float* __restrict__ pos, float* __restrict__ out, int N) {
    int i = blockIdx.x * blockDim.x + threadIdx.x;
    if (i < N * 3) out[i] = pos[i] + g_DELTA[i];
}

// ---------------------------------------------------------------------------
extern "C" void kernel_launch(void* const* d_in, const int* in_sizes, int n_in,
                              void* d_out, int out_size) {
    const float* x     = (const float*)d_in[0];
    const float* pos   = (const float*)d_in[1];
    const void*  ei    = d_in[2];
    const float* ew1   = (const float*)d_in[3];
    const float* eb1   = (const float*)d_in[4];
    const float* ew2   = (const float*)d_in[5];
    const float* eb2   = (const float*)d_in[6];
    const float* nw1   = (const float*)d_in[7];
    const float* nb1   = (const float*)d_in[8];
    const float* nw2   = (const float*)d_in[9];
    const float* nb2   = (const float*)d_in[10];
    const float* cw    = (const float*)d_in[11];
    const float* cb    = (const float*)d_in[12];
    const float* gamma = (const float*)d_in[13];
    const float* beta  = (const float*)d_in[14];

    int N = in_sizes[0] / F;
    int E = in_sizes[2] / 2;

    float* xout = (float*)d_out;
    float* pout = (float*)d_out + (size_t)N * F;

    float* XA;   cudaGetSymbolAddress((void**)&XA,   g_XA);
    float* XB;   cudaGetSymbolAddress((void**)&XB,   g_XB);
    float* AGGS; cudaGetSymbolAddress((void**)&AGGS, g_AGGS);
    float* DEG;  cudaGetSymbolAddress((void**)&DEG,  g_DEG);

    cudaFuncSetAttribute(gemm_rt<0>, cudaFuncAttributeMaxDynamicSharedMemorySize, SM_RT_TOTAL);
    cudaFuncSetAttribute(gemm_rt<1>, cudaFuncAttributeMaxDynamicSharedMemorySize, SM_RT_TOTAL);

    int tcb = (N + 127) / 128;
    int eb256 = (E + 255) / 256;

    detect_kernel<<<1, 256>>>(ei, E, N);
    prep_vc<<<1, 128>>>(ew2, cw, eb2, cb);
    zero_kernel<<<2048, 256>>>(N);

    // Sort edges by destination row (also produces DEG)
    zero_cnt<<<(N + 255) / 256, 256>>>(N);
    hist_kernel<<<eb256, 256>>>(ei, E);
    scan_kernel<<<1, 1024>>>(N);
    scatter_kernel<<<eb256, 256>>>(ei, E);

    // XA = x @ W1a + eb1 AND XB = x @ W1b — one merged launch
    gemm_rt<0><<<dim3(tcb, 2), 256, SM_RT_TOTAL>>>(
        x, ew1, eb1, XA, ew1 + 128 * F, nullptr, XB, nullptr, nullptr, N);

    // Edge stage over sorted edges (run-coalesced REDs, L1-hot XA)
    int ngroups = (E + 7) / 8;
    int eblocks = (ngroups * 32 + 255) / 256;
    edge_sorted<<<eblocks, 256>>>(pos, ew1, E);

    // AGG = AGGS @ ew2 + deg*eb2  -> XA
    gemm_rt<0><<<tcb, 256, SM_RT_TOTAL>>>(AGGS, ew2, nullptr, XA,
                                          nullptr, nullptr, nullptr, DEG, eb2, N);
    // H = silu(AGG @ nw1 + nb1)   -> XB
    gemm_rt<1><<<tcb, 256, SM_RT_TOTAL>>>(XA, nw1, nb1, XB,
                                          nullptr, nullptr, nullptr, nullptr, nullptr, N);
    // P = H @ nw2 + nb2           -> AGGS (reuse)
    gemm_rt<0><<<tcb, 256, SM_RT_TOTAL>>>(XB, nw2, nb2, AGGS,
                                          nullptr, nullptr, nullptr, nullptr, nullptr, N);
    // x_out = LN(x + P)
    ln_kernel<<<(N + 7) / 8, 256>>>(AGGS, x, gamma, beta, xout, N);
    // pos_out
    pos_kernel<<<(N * 3 + 255) / 256, 256>>>(pos, pout, N);
}

// round 12
// speedup vs baseline: 1.1642x; 1.1642x over previous
#include <cuda_runtime.h>
#include <cuda_bf16.h>
#include <math.h>
#include <stdint.h>

#define NMAX 50048
#define F 128
#define LN_EPS 1e-5f

// ---------------------------------------------------------------------------
// Scratch (device globals — no allocation allowed)
__device__ float g_XA[NMAX * F];
__device__ float g_XB[NMAX * F];
__device__ float g_AGGS[NMAX * F];
__device__ float g_DELTA[NMAX * 3];
__device__ float g_DEG[NMAX];
__device__ float g_V[F];
__device__ float g_C0;
__device__ int   g_IS64;

// ---------------------------------------------------------------------------
#define FFMA2(acc, a, b) \
    asm("fma.rn.f32x2 %0, %1, %2, %0;" : "+l"(acc) : "l"(a), "l"(b))
__device__ __forceinline__ unsigned long long pack2(float v) {
    unsigned long long r;
    unsigned int u = __float_as_uint(v);
    asm("mov.b64 %0, {%1, %1};" : "=l"(r) : "r"(u));
    return r;
}
__device__ __forceinline__ void unpack2(unsigned long long p, float& lo, float& hi) {
    unsigned int a, b;
    asm("mov.b64 {%0, %1}, %2;" : "=r"(a), "=r"(b) : "l"(p));
    lo = __uint_as_float(a);
    hi = __uint_as_float(b);
}
__device__ __forceinline__ uint32_t smem_u32(const void* p) {
    uint32_t a;
    asm("{ .reg .u64 t; cvta.to.shared.u64 t, %1; cvt.u32.u64 %0, t; }"
        : "=r"(a) : "l"(p));
    return a;
}
#define CP_ASYNC16(dst, src) \
    asm volatile("cp.async.cg.shared.global [%0], [%1], 16;" :: "r"(dst), "l"(src))
#define CP_COMMIT() asm volatile("cp.async.commit_group;" ::: "memory")
#define CP_WAIT0()  asm volatile("cp.async.wait_group 0;" ::: "memory")

__device__ __forceinline__ float fast_sigmoid(float p) {
    return __fdividef(1.f, 1.f + __expf(-p));
}
__device__ __forceinline__ float fast_tanh(float x) {
    return 1.f - __fdividef(2.f, __expf(2.f * x) + 1.f);
}

// ---------------------------------------------------------------------------
__global__ void detect_kernel(const void* ei, int E, int N) {
    __shared__ int bad;
    if (threadIdx.x == 0) bad = 0;
    __syncthreads();
    int cnt = (2 * E < 256) ? 2 * E : 256;
    if ((int)threadIdx.x < cnt) {
        long long v = ((const long long*)ei)[threadIdx.x];
        if (v < 0 || v >= N) bad = 1;
    }
    __syncthreads();
    if (threadIdx.x == 0) g_IS64 = !bad;
}

__global__ void prep_vc(const float* __restrict__ ew2, const float* __restrict__ cw,
                        const float* __restrict__ eb2, const float* __restrict__ cb) {
    int t = threadIdx.x;
    float s = 0.f;
    for (int o = 0; o < F; o++) s += ew2[t * F + o] * cw[o];
    g_V[t] = s;
    if (t == 0) {
        float c = cb[0];
        for (int o = 0; o < F; o++) c += eb2[o] * cw[o];
        g_C0 = c;
    }
}

__global__ void zero_kernel(int N) {
    int n4 = N * 32;
    float4 z4 = make_float4(0.f, 0.f, 0.f, 0.f);
    float4* a4 = (float4*)g_AGGS;
    int stride = gridDim.x * blockDim.x;
    for (int i = blockIdx.x * blockDim.x + threadIdx.x; i < n4; i += stride) a4[i] = z4;
    for (int i = blockIdx.x * blockDim.x + threadIdx.x; i < N * 3; i += stride) g_DELTA[i] = 0.f;
    for (int i = blockIdx.x * blockDim.x + threadIdx.x; i < N; i += stride) g_DEG[i] = 0.f;
}

// ---------------------------------------------------------------------------
// Edge kernel: one warp per edge, v4 RED scatter (proven best structure).
__global__ void __launch_bounds__(256)
edge_kernel(const void* __restrict__ ei_raw, const float* __restrict__ pos,
            const float* __restrict__ ew1, int E, int N) {
    int gw = (blockIdx.x * blockDim.x + threadIdx.x) >> 5;
    int lane = threadIdx.x & 31;
    if (gw >= E) return;

    int row, col;
    if (g_IS64) {
        const long long* ei = (const long long*)ei_raw;
        row = (int)ei[gw];
        col = (int)ei[(size_t)E + gw];
    } else {
        const int* ei = (const int*)ei_raw;
        row = ei[gw];
        col = ei[E + gw];
    }

    float dx = pos[row * 3 + 0] - pos[col * 3 + 0];
    float dy = pos[row * 3 + 1] - pos[col * 3 + 1];
    float dz = pos[row * 3 + 2] - pos[col * 3 + 2];
    float dist2 = dx * dx + dy * dy + dz * dz;

    const float4* XA4 = (const float4*)g_XA;
    const float4* XB4 = (const float4*)g_XB;
    float4 a = XA4[(size_t)row * 32 + lane];
    float4 b = XB4[(size_t)col * 32 + lane];
    float4 w = __ldg((const float4*)(ew1 + 256 * F) + lane);

    float p0 = a.x + b.x + dist2 * w.x;
    float p1 = a.y + b.y + dist2 * w.y;
    float p2 = a.z + b.z + dist2 * w.z;
    float p3 = a.w + b.w + dist2 * w.w;

    float s0 = p0 * fast_sigmoid(p0);
    float s1 = p1 * fast_sigmoid(p1);
    float s2 = p2 * fast_sigmoid(p2);
    float s3 = p3 * fast_sigmoid(p3);

    float* aggp = g_AGGS + (size_t)row * F + lane * 4;
    asm volatile("red.global.add.v4.f32 [%0], {%1, %2, %3, %4};"
                 :: "l"(aggp), "f"(s0), "f"(s1), "f"(s2), "f"(s3) : "memory");

    float4 vv = ((const float4*)g_V)[lane];
    float d = s0 * vv.x + s1 * vv.y + s2 * vv.z + s3 * vv.w;
#pragma unroll
    for (int o = 16; o > 0; o >>= 1) d += __shfl_xor_sync(0xffffffffu, d, o);

    if (lane == 0) {
        float sc = fast_tanh(d + g_C0);
        atomicAdd(&g_DELTA[row * 3 + 0], sc * dx);
        atomicAdd(&g_DELTA[row * 3 + 1], sc * dy);
        atomicAdd(&g_DELTA[row * 3 + 2], sc * dz);
        atomicAdd(&g_DEG[row], 1.0f);
    }
}

// ---------------------------------------------------------------------------
// Pipelined register-tiled GEMM. Optional fused residual+LayerNorm epilogue
// (lnx != nullptr): pre = acc + bias + lnx[row], out = gamma*(pre-mu)*ri + beta.
#define AS_STRIDE 132
#define WS_BYTES  16384
#define AS_BYTES  16896
#define SM_AS0    (2 * WS_BYTES)
#define SM_RT_TOTAL (2 * WS_BYTES + 2 * AS_BYTES)

template <int ACT>
__global__ void __launch_bounds__(256, 2)
gemm_rt(const float* __restrict__ A,
        const float* __restrict__ W0, const float* __restrict__ bias0,
        float* __restrict__ out0,
        const float* __restrict__ W1, const float* __restrict__ bias1,
        float* __restrict__ out1,
        const float* __restrict__ deg, const float* __restrict__ degvec,
        const float* __restrict__ lnx, const float* __restrict__ gamma,
        const float* __restrict__ beta, int N) {
    extern __shared__ char smem[];

    const float* W = W0;
    const float* bias = bias0;
    float* out = out0;
    if (blockIdx.y == 1) { W = W1; bias = bias1; out = out1; }

    int t = threadIdx.x;
    int lane = t & 31, w = t >> 5;
    int txl = lane & 3, tyl = lane >> 2;
    int wx = w & 3, wy = w >> 2;
    int col0 = (wx * 4 + txl) * 8;
    int rowt = (wy * 8 + tyl) * 8;
    int row0 = blockIdx.x * 128;

    uint32_t sb = smem_u32(smem);

    int arl = (w & 3) * 32 + lane;
    int kh  = (w >> 2) * 16;
    int arow = row0 + arl;
    const float4* Abase = (const float4*)(A + (size_t)arow * F);

    int wk = t >> 3, wcol = (t & 7) * 16;

    unsigned long long acc[8][4];
#pragma unroll
    for (int r = 0; r < 8; r++)
#pragma unroll
        for (int c = 0; c < 4; c++) acc[r][c] = 0ull;

    float4 v[4];

    {
        const float* wsrc = W + (size_t)wk * F + wcol;
        uint32_t wdst = sb + (uint32_t)(wk * F + wcol) * 4;
#pragma unroll
        for (int q = 0; q < 4; q++) CP_ASYNC16(wdst + q * 16, wsrc + q * 4);
        CP_COMMIT();
        if (arow < N) {
#pragma unroll
            for (int q = 0; q < 4; q++) v[q] = __ldg(&Abase[(kh >> 2) + q]);
        } else {
#pragma unroll
            for (int q = 0; q < 4; q++) v[q] = make_float4(0.f, 0.f, 0.f, 0.f);
        }
        float* As0 = (float*)(smem + SM_AS0);
#pragma unroll
        for (int q = 0; q < 4; q++) {
            float vals[4] = {v[q].x, v[q].y, v[q].z, v[q].w};
#pragma unroll
            for (int e = 0; e < 4; e++)
                As0[(kh + q * 4 + e) * AS_STRIDE + arl] = vals[e];
        }
        CP_WAIT0();
    }
    __syncthreads();

#pragma unroll 1
    for (int c = 0; c < 4; c++) {
        int cb = c & 1, nb = (c + 1) & 1;
        float* Ws = (float*)(smem + cb * WS_BYTES);
        float* As = (float*)(smem + SM_AS0 + cb * AS_BYTES);

        if (c < 3) {
            const float* wsrc = W + (size_t)((c + 1) * 32 + wk) * F + wcol;
            uint32_t wdst = sb + (uint32_t)nb * WS_BYTES + (uint32_t)(wk * F + wcol) * 4;
#pragma unroll
            for (int q = 0; q < 4; q++) CP_ASYNC16(wdst + q * 16, wsrc + q * 4);
            CP_COMMIT();
            if (arow < N) {
                int kb = ((c + 1) * 32 + kh) >> 2;
#pragma unroll
                for (int q = 0; q < 4; q++) v[q] = __ldg(&Abase[kb + q]);
            }
        }

#pragma unroll
        for (int kk = 0; kk < 32; kk++) {
            float4 al = *(const float4*)&As[kk * AS_STRIDE + rowt];
            float4 ah = *(const float4*)&As[kk * AS_STRIDE + rowt + 4];
            unsigned long long a0 = pack2(al.x), a1 = pack2(al.y);
            unsigned long long a2 = pack2(al.z), a3 = pack2(al.w);
            unsigned long long a4 = pack2(ah.x), a5 = pack2(ah.y);
            unsigned long long a6 = pack2(ah.z), a7 = pack2(ah.w);
            ulonglong2 bv0 = *(const ulonglong2*)&Ws[kk * F + col0];
            ulonglong2 bv1 = *(const ulonglong2*)&Ws[kk * F + col0 + 4];
            FFMA2(acc[0][0], a0, bv0.x); FFMA2(acc[0][1], a0, bv0.y);
            FFMA2(acc[0][2], a0, bv1.x); FFMA2(acc[0][3], a0, bv1.y);
            FFMA2(acc[1][0], a1, bv0.x); FFMA2(acc[1][1], a1, bv0.y);
            FFMA2(acc[1][2], a1, bv1.x); FFMA2(acc[1][3], a1, bv1.y);
            FFMA2(acc[2][0], a2, bv0.x); FFMA2(acc[2][1], a2, bv0.y);
            FFMA2(acc[2][2], a2, bv1.x); FFMA2(acc[2][3], a2, bv1.y);
            FFMA2(acc[3][0], a3, bv0.x); FFMA2(acc[3][1], a3, bv0.y);
            FFMA2(acc[3][2], a3, bv1.x); FFMA2(acc[3][3], a3, bv1.y);
            FFMA2(acc[4][0], a4, bv0.x); FFMA2(acc[4][1], a4, bv0.y);
            FFMA2(acc[4][2], a4, bv1.x); FFMA2(acc[4][3], a4, bv1.y);
            FFMA2(acc[5][0], a5, bv0.x); FFMA2(acc[5][1], a5, bv0.y);
            FFMA2(acc[5][2], a5, bv1.x); FFMA2(acc[5][3], a5, bv1.y);
            FFMA2(acc[6][0], a6, bv0.x); FFMA2(acc[6][1], a6, bv0.y);
            FFMA2(acc[6][2], a6, bv1.x); FFMA2(acc[6][3], a6, bv1.y);
            FFMA2(acc[7][0], a7, bv0.x); FFMA2(acc[7][1], a7, bv0.y);
            FFMA2(acc[7][2], a7, bv1.x); FFMA2(acc[7][3], a7, bv1.y);
        }

        if (c < 3) {
            float* Asn = (float*)(smem + SM_AS0 + nb * AS_BYTES);
            if (arow >= N) {
#pragma unroll
                for (int q = 0; q < 4; q++) v[q] = make_float4(0.f, 0.f, 0.f, 0.f);
            }
#pragma unroll
            for (int q = 0; q < 4; q++) {
                float vals[4] = {v[q].x, v[q].y, v[q].z, v[q].w};
#pragma unroll
                for (int e = 0; e < 4; e++)
                    Asn[(kh + q * 4 + e) * AS_STRIDE + arl] = vals[e];
            }
            CP_WAIT0();
        }
        __syncthreads();
    }

    float bcol[8];
#pragma unroll
    for (int j = 0; j < 8; j++)
        bcol[j] = bias ? __ldg(&bias[col0 + j]) : 0.f;

    if (lnx == nullptr) {
        // Standard epilogue (optional deg*degvec, optional silu)
        float dcol[8];
#pragma unroll
        for (int j = 0; j < 8; j++)
            dcol[j] = degvec ? __ldg(&degvec[col0 + j]) : 0.f;
#pragma unroll
        for (int rr = 0; rr < 8; rr++) {
            int row = row0 + rowt + rr;
            if (row < N) {
                float dg = deg ? deg[row] : 0.f;
                float o[8];
#pragma unroll
                for (int cp = 0; cp < 4; cp++) unpack2(acc[rr][cp], o[2 * cp], o[2 * cp + 1]);
#pragma unroll
                for (int j = 0; j < 8; j++) {
                    float vv2 = o[j] + bcol[j] + dg * dcol[j];
                    if (ACT == 1) vv2 = vv2 * fast_sigmoid(vv2);
                    o[j] = vv2;
                }
                float4* op = (float4*)(out + (size_t)row * F + col0);
                op[0] = make_float4(o[0], o[1], o[2], o[3]);
                op[1] = make_float4(o[4], o[5], o[6], o[7]);
            }
        }
    } else {
        // Fused residual + LayerNorm epilogue.
        // Reuse smem (compute finished, synced): part[128][16][2] = 16KB at 0,
        // mu[128] at 16384, ri[128] at 16896.
        float* part = (float*)smem;
        float* smu = (float*)(smem + 16384);
        float* sri = (float*)(smem + 16896);
        int cg = wx * 4 + txl;  // 0..15 column group

        float gcol[8], becol[8];
#pragma unroll
        for (int j = 0; j < 8; j++) {
            gcol[j]  = __ldg(&gamma[col0 + j]);
            becol[j] = __ldg(&beta[col0 + j]);
        }

        // pass1: per-thread partial sums of pre = acc + bias + x
#pragma unroll
        for (int rr = 0; rr < 8; rr++) {
            int row = row0 + rowt + rr;
            float s = 0.f, s2 = 0.f;
            if (row < N) {
                float o[8];
#pragma unroll
                for (int cp = 0; cp < 4; cp++) unpack2(acc[rr][cp], o[2 * cp], o[2 * cp + 1]);
                const float4* xp = (const float4*)(lnx + (size_t)row * F + col0);
                float4 x0 = __ldg(&xp[0]), x1 = __ldg(&xp[1]);
                float xv[8] = {x0.x, x0.y, x0.z, x0.w, x1.x, x1.y, x1.z, x1.w};
#pragma unroll
                for (int j = 0; j < 8; j++) {
                    float p = o[j] + bcol[j] + xv[j];
                    s += p;
                    s2 += p * p;
                }
            }
            part[((rowt + rr) * 16 + cg) * 2 + 0] = s;
            part[((rowt + rr) * 16 + cg) * 2 + 1] = s2;
        }
        __syncthreads();

        // pass2a: 2 threads per row reduce 16 partials -> mu/ri
        {
            int row = t >> 1, half = t & 1;
            float s = 0.f, s2 = 0.f;
#pragma unroll
            for (int q = 0; q < 8; q++) {
                s  += part[(row * 16 + half * 8 + q) * 2 + 0];
                s2 += part[(row * 16 + half * 8 + q) * 2 + 1];
            }
            s  += __shfl_xor_sync(0xffffffffu, s, 1);
            s2 += __shfl_xor_sync(0xffffffffu, s2, 1);
            if (half == 0) {
                float mean = s * (1.f / F);
                smu[row] = mean;
                sri[row] = rsqrtf(s2 * (1.f / F) - mean * mean + LN_EPS);
            }
        }
        __syncthreads();

        // pass2b: normalize and store
#pragma unroll
        for (int rr = 0; rr < 8; rr++) {
            int row = row0 + rowt + rr;
            if (row < N) {
                float mu = smu[rowt + rr];
                float ri = sri[rowt + rr];
                float o[8];
#pragma unroll
                for (int cp = 0; cp < 4; cp++) unpack2(acc[rr][cp], o[2 * cp], o[2 * cp + 1]);
                const float4* xp = (const float4*)(lnx + (size_t)row * F + col0);
                float4 x0 = __ldg(&xp[0]), x1 = __ldg(&xp[1]);
                float xv[8] = {x0.x, x0.y, x0.z, x0.w, x1.x, x1.y, x1.z, x1.w};
#pragma unroll
                for (int j = 0; j < 8; j++) {
                    float p = o[j] + bcol[j] + xv[j];
                    o[j] = gcol[j] * (p - mu) * ri + becol[j];
                }
                float4* op = (float4*)(out + (size_t)row * F + col0);
                op[0] = make_float4(o[0], o[1], o[2], o[3]);
                op[1] = make_float4(o[4], o[5], o[6], o[7]);
            }
        }
    }
}

// ---------------------------------------------------------------------------
__global__ void pos_kernel(const float* __restrict__ pos, float* __restrict__ out, int N) {
    int i = blockIdx.x * blockDim.x + threadIdx.x;
    if (i < N * 3) out[i] = pos[i] + g_DELTA[i];
}

// ---------------------------------------------------------------------------
extern "C" void kernel_launch(void* const* d_in, const int* in_sizes, int n_in,
                              void* d_out, int out_size) {
    const float* x     = (const float*)d_in[0];
    const float* pos   = (const float*)d_in[1];
    const void*  ei    = d_in[2];
    const float* ew1   = (const float*)d_in[3];
    const float* eb1   = (const float*)d_in[4];
    const float* ew2   = (const float*)d_in[5];
    const float* eb2   = (const float*)d_in[6];
    const float* nw1   = (const float*)d_in[7];
    const float* nb1   = (const float*)d_in[8];
    const float* nw2   = (const float*)d_in[9];
    const float* nb2   = (const float*)d_in[10];
    const float* cw    = (const float*)d_in[11];
    const float* cb    = (const float*)d_in[12];
    const float* gamma = (const float*)d_in[13];
    const float* beta  = (const float*)d_in[14];

    int N = in_sizes[0] / F;
    int E = in_sizes[2] / 2;

    float* xout = (float*)d_out;
    float* pout = (float*)d_out + (size_t)N * F;

    float* XA;   cudaGetSymbolAddress((void**)&XA,   g_XA);
    float* XB;   cudaGetSymbolAddress((void**)&XB,   g_XB);
    float* AGGS; cudaGetSymbolAddress((void**)&AGGS, g_AGGS);
    float* DEG;  cudaGetSymbolAddress((void**)&DEG,  g_DEG);

    cudaFuncSetAttribute(gemm_rt<0>, cudaFuncAttributeMaxDynamicSharedMemorySize, SM_RT_TOTAL);
    cudaFuncSetAttribute(gemm_rt<1>, cudaFuncAttributeMaxDynamicSharedMemorySize, SM_RT_TOTAL);

    int tcb = (N + 127) / 128;

    detect_kernel<<<1, 256>>>(ei, E, N);
    prep_vc<<<1, 128>>>(ew2, cw, eb2, cb);
    zero_kernel<<<2048, 256>>>(N);

    // XA = x @ W1a + eb1 AND XB = x @ W1b — one merged launch
    gemm_rt<0><<<dim3(tcb, 2), 256, SM_RT_TOTAL>>>(
        x, ew1, eb1, XA, ew1 + 128 * F, nullptr, XB,
        nullptr, nullptr, nullptr, nullptr, nullptr, N);

    // Edge stage
    int eblocks = (E * 32 + 255) / 256;
    edge_kernel<<<eblocks, 256>>>(ei, pos, ew1, E, N);

    // AGG = AGGS @ ew2 + deg*eb2  -> XA
    gemm_rt<0><<<tcb, 256, SM_RT_TOTAL>>>(AGGS, ew2, nullptr, XA,
                                          nullptr, nullptr, nullptr,
                                          DEG, eb2, nullptr, nullptr, nullptr, N);
    // H = silu(AGG @ nw1 + nb1)   -> XB
    gemm_rt<1><<<tcb, 256, SM_RT_TOTAL>>>(XA, nw1, nb1, XB,
                                          nullptr, nullptr, nullptr,
                                          nullptr, nullptr, nullptr, nullptr, nullptr, N);
    // x_out = LN(x + H @ nw2 + nb2)  — fused residual+LN epilogue
    gemm_rt<0><<<tcb, 256, SM_RT_TOTAL>>>(XB, nw2, nb2, xout,
                                          nullptr, nullptr, nullptr,
                                          nullptr, nullptr, x, gamma, beta, N);
    // pos_out
    pos_kernel<<<(N * 3 + 255) / 256, 256>>>(pos, pout, N);
}

// round 13
// speedup vs baseline: 1.2243x; 1.0516x over previous
#include <cuda_runtime.h>
#include <cuda_bf16.h>
#include <math.h>
#include <stdint.h>

#define NMAX 50048
#define F 128
#define LN_EPS 1e-5f

// ---------------------------------------------------------------------------
// Scratch (device globals — no allocation allowed)
__device__ float g_XA[NMAX * F];
__device__ float g_XB[NMAX * F];
__device__ float g_AGGS[NMAX * F];
__device__ float g_DELTA[NMAX * 3];
__device__ float g_DEG[NMAX];
__device__ float g_V[F];
__device__ float g_C0;
__device__ int   g_IS64;

// ---------------------------------------------------------------------------
#define FFMA2(acc, a, b) \
    asm("fma.rn.f32x2 %0, %1, %2, %0;" : "+l"(acc) : "l"(a), "l"(b))
__device__ __forceinline__ unsigned long long pack2(float v) {
    unsigned long long r;
    unsigned int u = __float_as_uint(v);
    asm("mov.b64 %0, {%1, %1};" : "=l"(r) : "r"(u));
    return r;
}
__device__ __forceinline__ void unpack2(unsigned long long p, float& lo, float& hi) {
    unsigned int a, b;
    asm("mov.b64 {%0, %1}, %2;" : "=r"(a), "=r"(b) : "l"(p));
    lo = __uint_as_float(a);
    hi = __uint_as_float(b);
}
__device__ __forceinline__ uint32_t smem_u32(const void* p) {
    uint32_t a;
    asm("{ .reg .u64 t; cvta.to.shared.u64 t, %1; cvt.u32.u64 %0, t; }"
        : "=r"(a) : "l"(p));
    return a;
}
#define CP_ASYNC16(dst, src) \
    asm volatile("cp.async.cg.shared.global [%0], [%1], 16;" :: "r"(dst), "l"(src))
#define CP_COMMIT() asm volatile("cp.async.commit_group;" ::: "memory")
#define CP_WAIT0()  asm volatile("cp.async.wait_group 0;" ::: "memory")

__device__ __forceinline__ float fast_sigmoid(float p) {
    return __fdividef(1.f, 1.f + __expf(-p));
}
__device__ __forceinline__ float fast_tanh(float x) {
    return 1.f - __fdividef(2.f, __expf(2.f * x) + 1.f);
}

// ---------------------------------------------------------------------------
__global__ void detect_kernel(const void* ei, int E, int N) {
    __shared__ int bad;
    if (threadIdx.x == 0) bad = 0;
    __syncthreads();
    int cnt = (2 * E < 256) ? 2 * E : 256;
    if ((int)threadIdx.x < cnt) {
        long long v = ((const long long*)ei)[threadIdx.x];
        if (v < 0 || v >= N) bad = 1;
    }
    __syncthreads();
    if (threadIdx.x == 0) g_IS64 = !bad;
}

__global__ void prep_vc(const float* __restrict__ ew2, const float* __restrict__ cw,
                        const float* __restrict__ eb2, const float* __restrict__ cb) {
    int t = threadIdx.x;
    float s = 0.f;
    for (int o = 0; o < F; o++) s += ew2[t * F + o] * cw[o];
    g_V[t] = s;
    if (t == 0) {
        float c = cb[0];
        for (int o = 0; o < F; o++) c += eb2[o] * cw[o];
        g_C0 = c;
    }
}

__global__ void zero_kernel(int N) {
    int n4 = N * 32;
    float4 z4 = make_float4(0.f, 0.f, 0.f, 0.f);
    float4* a4 = (float4*)g_AGGS;
    int stride = gridDim.x * blockDim.x;
    for (int i = blockIdx.x * blockDim.x + threadIdx.x; i < n4; i += stride) a4[i] = z4;
    for (int i = blockIdx.x * blockDim.x + threadIdx.x; i < N * 3; i += stride) g_DELTA[i] = 0.f;
    for (int i = blockIdx.x * blockDim.x + threadIdx.x; i < N; i += stride) g_DEG[i] = 0.f;
}

// ---------------------------------------------------------------------------
// Edge kernel: one warp per edge, v4 RED scatter (proven best structure).
__global__ void __launch_bounds__(256)
edge_kernel(const void* __restrict__ ei_raw, const float* __restrict__ pos,
            const float* __restrict__ ew1, int E, int N) {
    int gw = (blockIdx.x * blockDim.x + threadIdx.x) >> 5;
    int lane = threadIdx.x & 31;
    if (gw >= E) return;

    int row, col;
    if (g_IS64) {
        const long long* ei = (const long long*)ei_raw;
        row = (int)ei[gw];
        col = (int)ei[(size_t)E + gw];
    } else {
        const int* ei = (const int*)ei_raw;
        row = ei[gw];
        col = ei[E + gw];
    }

    float dx = pos[row * 3 + 0] - pos[col * 3 + 0];
    float dy = pos[row * 3 + 1] - pos[col * 3 + 1];
    float dz = pos[row * 3 + 2] - pos[col * 3 + 2];
    float dist2 = dx * dx + dy * dy + dz * dz;

    const float4* XA4 = (const float4*)g_XA;
    const float4* XB4 = (const float4*)g_XB;
    float4 a = XA4[(size_t)row * 32 + lane];
    float4 b = XB4[(size_t)col * 32 + lane];
    float4 w = __ldg((const float4*)(ew1 + 256 * F) + lane);

    float p0 = a.x + b.x + dist2 * w.x;
    float p1 = a.y + b.y + dist2 * w.y;
    float p2 = a.z + b.z + dist2 * w.z;
    float p3 = a.w + b.w + dist2 * w.w;

    float s0 = p0 * fast_sigmoid(p0);
    float s1 = p1 * fast_sigmoid(p1);
    float s2 = p2 * fast_sigmoid(p2);
    float s3 = p3 * fast_sigmoid(p3);

    float* aggp = g_AGGS + (size_t)row * F + lane * 4;
    asm volatile("red.global.add.v4.f32 [%0], {%1, %2, %3, %4};"
                 :: "l"(aggp), "f"(s0), "f"(s1), "f"(s2), "f"(s3) : "memory");

    float4 vv = ((const float4*)g_V)[lane];
    float d = s0 * vv.x + s1 * vv.y + s2 * vv.z + s3 * vv.w;
#pragma unroll
    for (int o = 16; o > 0; o >>= 1) d += __shfl_xor_sync(0xffffffffu, d, o);

    if (lane == 0) {
        float sc = fast_tanh(d + g_C0);
        atomicAdd(&g_DELTA[row * 3 + 0], sc * dx);
        atomicAdd(&g_DELTA[row * 3 + 1], sc * dy);
        atomicAdd(&g_DELTA[row * 3 + 2], sc * dz);
        atomicAdd(&g_DEG[row], 1.0f);
    }
}

// ---------------------------------------------------------------------------
// Pipelined register-tiled GEMM. LNFUSE is a COMPILE-TIME switch: LNFUSE=0
// instantiations are byte-identical to the proven R10 kernel (dead params).
#define AS_STRIDE 132
#define WS_BYTES  16384
#define AS_BYTES  16896
#define SM_AS0    (2 * WS_BYTES)
#define SM_RT_TOTAL (2 * WS_BYTES + 2 * AS_BYTES)

template <int ACT, int LNFUSE>
__global__ void __launch_bounds__(256, 2)
gemm_rt(const float* __restrict__ A,
        const float* __restrict__ W0, const float* __restrict__ bias0,
        float* __restrict__ out0,
        const float* __restrict__ W1, const float* __restrict__ bias1,
        float* __restrict__ out1,
        const float* __restrict__ deg, const float* __restrict__ degvec,
        const float* __restrict__ lnx, const float* __restrict__ gamma,
        const float* __restrict__ beta, int N) {
    extern __shared__ char smem[];

    const float* W = W0;
    const float* bias = bias0;
    float* out = out0;
    if (blockIdx.y == 1) { W = W1; bias = bias1; out = out1; }

    int t = threadIdx.x;
    int lane = t & 31, w = t >> 5;
    int txl = lane & 3, tyl = lane >> 2;
    int wx = w & 3, wy = w >> 2;
    int col0 = (wx * 4 + txl) * 8;
    int rowt = (wy * 8 + tyl) * 8;
    int row0 = blockIdx.x * 128;

    uint32_t sb = smem_u32(smem);

    int arl = (w & 3) * 32 + lane;
    int kh  = (w >> 2) * 16;
    int arow = row0 + arl;
    const float4* Abase = (const float4*)(A + (size_t)arow * F);

    int wk = t >> 3, wcol = (t & 7) * 16;

    unsigned long long acc[8][4];
#pragma unroll
    for (int r = 0; r < 8; r++)
#pragma unroll
        for (int c = 0; c < 4; c++) acc[r][c] = 0ull;

    float4 v[4];

    {
        const float* wsrc = W + (size_t)wk * F + wcol;
        uint32_t wdst = sb + (uint32_t)(wk * F + wcol) * 4;
#pragma unroll
        for (int q = 0; q < 4; q++) CP_ASYNC16(wdst + q * 16, wsrc + q * 4);
        CP_COMMIT();
        if (arow < N) {
#pragma unroll
            for (int q = 0; q < 4; q++) v[q] = __ldg(&Abase[(kh >> 2) + q]);
        } else {
#pragma unroll
            for (int q = 0; q < 4; q++) v[q] = make_float4(0.f, 0.f, 0.f, 0.f);
        }
        float* As0 = (float*)(smem + SM_AS0);
#pragma unroll
        for (int q = 0; q < 4; q++) {
            float vals[4] = {v[q].x, v[q].y, v[q].z, v[q].w};
#pragma unroll
            for (int e = 0; e < 4; e++)
                As0[(kh + q * 4 + e) * AS_STRIDE + arl] = vals[e];
        }
        CP_WAIT0();
    }
    __syncthreads();

#pragma unroll 1
    for (int c = 0; c < 4; c++) {
        int cb = c & 1, nb = (c + 1) & 1;
        float* Ws = (float*)(smem + cb * WS_BYTES);
        float* As = (float*)(smem + SM_AS0 + cb * AS_BYTES);

        if (c < 3) {
            const float* wsrc = W + (size_t)((c + 1) * 32 + wk) * F + wcol;
            uint32_t wdst = sb + (uint32_t)nb * WS_BYTES + (uint32_t)(wk * F + wcol) * 4;
#pragma unroll
            for (int q = 0; q < 4; q++) CP_ASYNC16(wdst + q * 16, wsrc + q * 4);
            CP_COMMIT();
            if (arow < N) {
                int kb = ((c + 1) * 32 + kh) >> 2;
#pragma unroll
                for (int q = 0; q < 4; q++) v[q] = __ldg(&Abase[kb + q]);
            }
        }

#pragma unroll
        for (int kk = 0; kk < 32; kk++) {
            float4 al = *(const float4*)&As[kk * AS_STRIDE + rowt];
            float4 ah = *(const float4*)&As[kk * AS_STRIDE + rowt + 4];
            unsigned long long a0 = pack2(al.x), a1 = pack2(al.y);
            unsigned long long a2 = pack2(al.z), a3 = pack2(al.w);
            unsigned long long a4 = pack2(ah.x), a5 = pack2(ah.y);
            unsigned long long a6 = pack2(ah.z), a7 = pack2(ah.w);
            ulonglong2 bv0 = *(const ulonglong2*)&Ws[kk * F + col0];
            ulonglong2 bv1 = *(const ulonglong2*)&Ws[kk * F + col0 + 4];
            FFMA2(acc[0][0], a0, bv0.x); FFMA2(acc[0][1], a0, bv0.y);
            FFMA2(acc[0][2], a0, bv1.x); FFMA2(acc[0][3], a0, bv1.y);
            FFMA2(acc[1][0], a1, bv0.x); FFMA2(acc[1][1], a1, bv0.y);
            FFMA2(acc[1][2], a1, bv1.x); FFMA2(acc[1][3], a1, bv1.y);
            FFMA2(acc[2][0], a2, bv0.x); FFMA2(acc[2][1], a2, bv0.y);
            FFMA2(acc[2][2], a2, bv1.x); FFMA2(acc[2][3], a2, bv1.y);
            FFMA2(acc[3][0], a3, bv0.x); FFMA2(acc[3][1], a3, bv0.y);
            FFMA2(acc[3][2], a3, bv1.x); FFMA2(acc[3][3], a3, bv1.y);
            FFMA2(acc[4][0], a4, bv0.x); FFMA2(acc[4][1], a4, bv0.y);
            FFMA2(acc[4][2], a4, bv1.x); FFMA2(acc[4][3], a4, bv1.y);
            FFMA2(acc[5][0], a5, bv0.x); FFMA2(acc[5][1], a5, bv0.y);
            FFMA2(acc[5][2], a5, bv1.x); FFMA2(acc[5][3], a5, bv1.y);
            FFMA2(acc[6][0], a6, bv0.x); FFMA2(acc[6][1], a6, bv0.y);
            FFMA2(acc[6][2], a6, bv1.x); FFMA2(acc[6][3], a6, bv1.y);
            FFMA2(acc[7][0], a7, bv0.x); FFMA2(acc[7][1], a7, bv0.y);
            FFMA2(acc[7][2], a7, bv1.x); FFMA2(acc[7][3], a7, bv1.y);
        }

        if (c < 3) {
            float* Asn = (float*)(smem + SM_AS0 + nb * AS_BYTES);
            if (arow >= N) {
#pragma unroll
                for (int q = 0; q < 4; q++) v[q] = make_float4(0.f, 0.f, 0.f, 0.f);
            }
#pragma unroll
            for (int q = 0; q < 4; q++) {
                float vals[4] = {v[q].x, v[q].y, v[q].z, v[q].w};
#pragma unroll
                for (int e = 0; e < 4; e++)
                    Asn[(kh + q * 4 + e) * AS_STRIDE + arl] = vals[e];
            }
            CP_WAIT0();
        }
        __syncthreads();
    }

    float bcol[8];
#pragma unroll
    for (int j = 0; j < 8; j++)
        bcol[j] = bias ? __ldg(&bias[col0 + j]) : 0.f;

    if (LNFUSE == 0) {
        // R10 epilogue (identical codegen for LNFUSE=0 instantiations)
        float dcol[8];
#pragma unroll
        for (int j = 0; j < 8; j++)
            dcol[j] = degvec ? __ldg(&degvec[col0 + j]) : 0.f;
#pragma unroll
        for (int rr = 0; rr < 8; rr++) {
            int row = row0 + rowt + rr;
            if (row < N) {
                float dg = deg ? deg[row] : 0.f;
                float o[8];
#pragma unroll
                for (int cp = 0; cp < 4; cp++) unpack2(acc[rr][cp], o[2 * cp], o[2 * cp + 1]);
#pragma unroll
                for (int j = 0; j < 8; j++) {
                    float vv2 = o[j] + bcol[j] + dg * dcol[j];
                    if (ACT == 1) vv2 = vv2 * fast_sigmoid(vv2);
                    o[j] = vv2;
                }
                float4* op = (float4*)(out + (size_t)row * F + col0);
                op[0] = make_float4(o[0], o[1], o[2], o[3]);
                op[1] = make_float4(o[4], o[5], o[6], o[7]);
            }
        }
    } else {
        // Fused residual + LayerNorm epilogue (compile-time specialized).
        // Reuse smem (compute finished, synced): part[128][16][2]=16KB, mu, ri.
        float* part = (float*)smem;
        float* smu = (float*)(smem + 16384);
        float* sri = (float*)(smem + 16896);
        int cg = wx * 4 + txl;

        // pass1: per-thread partial sums of pre = acc + bias + x
#pragma unroll
        for (int rr = 0; rr < 8; rr++) {
            int row = row0 + rowt + rr;
            float s = 0.f, s2 = 0.f;
            if (row < N) {
                float o[8];
#pragma unroll
                for (int cp = 0; cp < 4; cp++) unpack2(acc[rr][cp], o[2 * cp], o[2 * cp + 1]);
                const float4* xp = (const float4*)(lnx + (size_t)row * F + col0);
                float4 x0 = __ldg(&xp[0]), x1 = __ldg(&xp[1]);
                float xv[8] = {x0.x, x0.y, x0.z, x0.w, x1.x, x1.y, x1.z, x1.w};
#pragma unroll
                for (int j = 0; j < 8; j++) {
                    float p = o[j] + bcol[j] + xv[j];
                    s += p;
                    s2 += p * p;
                }
            }
            part[((rowt + rr) * 16 + cg) * 2 + 0] = s;
            part[((rowt + rr) * 16 + cg) * 2 + 1] = s2;
        }
        __syncthreads();

        // pass2a: 2 threads per row reduce 16 partials -> mu/ri
        {
            int row = t >> 1, half = t & 1;
            float s = 0.f, s2 = 0.f;
#pragma unroll
            for (int q = 0; q < 8; q++) {
                s  += part[(row * 16 + half * 8 + q) * 2 + 0];
                s2 += part[(row * 16 + half * 8 + q) * 2 + 1];
            }
            s  += __shfl_xor_sync(0xffffffffu, s, 1);
            s2 += __shfl_xor_sync(0xffffffffu, s2, 1);
            if (half == 0) {
                float mean = s * (1.f / F);
                smu[row] = mean;
                sri[row] = rsqrtf(s2 * (1.f / F) - mean * mean + LN_EPS);
            }
        }
        __syncthreads();

        // pass2b: normalize and store
        float gcol[8], becol[8];
#pragma unroll
        for (int j = 0; j < 8; j++) {
            gcol[j]  = __ldg(&gamma[col0 + j]);
            becol[j] = __ldg(&beta[col0 + j]);
        }
#pragma unroll
        for (int rr = 0; rr < 8; rr++) {
            int row = row0 + rowt + rr;
            if (row < N) {
                float mu = smu[rowt + rr];
                float ri = sri[rowt + rr];
                float o[8];
#pragma unroll
                for (int cp = 0; cp < 4; cp++) unpack2(acc[rr][cp], o[2 * cp], o[2 * cp + 1]);
                const float4* xp = (const float4*)(lnx + (size_t)row * F + col0);
                float4 x0 = __ldg(&xp[0]), x1 = __ldg(&xp[1]);
                float xv[8] = {x0.x, x0.y, x0.z, x0.w, x1.x, x1.y, x1.z, x1.w};
#pragma unroll
                for (int j = 0; j < 8; j++) {
                    float p = o[j] + bcol[j] + xv[j];
                    o[j] = gcol[j] * (p - mu) * ri + becol[j];
                }
                float4* op = (float4*)(out + (size_t)row * F + col0);
                op[0] = make_float4(o[0], o[1], o[2], o[3]);
                op[1] = make_float4(o[4], o[5], o[6], o[7]);
            }
        }
    }
}

// ---------------------------------------------------------------------------
__global__ void pos_kernel(const float* __restrict__ pos, float* __restrict__ out, int N) {
    int i = blockIdx.x * blockDim.x + threadIdx.x;
    if (i < N * 3) out[i] = pos[i] + g_DELTA[i];
}

// ---------------------------------------------------------------------------
extern "C" void kernel_launch(void* const* d_in, const int* in_sizes, int n_in,
                              void* d_out, int out_size) {
    const float* x     = (const float*)d_in[0];
    const float* pos   = (const float*)d_in[1];
    const void*  ei    = d_in[2];
    const float* ew1   = (const float*)d_in[3];
    const float* eb1   = (const float*)d_in[4];
    const float* ew2   = (const float*)d_in[5];
    const float* eb2   = (const float*)d_in[6];
    const float* nw1   = (const float*)d_in[7];
    const float* nb1   = (const float*)d_in[8];
    const float* nw2   = (const float*)d_in[9];
    const float* nb2   = (const float*)d_in[10];
    const float* cw    = (const float*)d_in[11];
    const float* cb    = (const float*)d_in[12];
    const float* gamma = (const float*)d_in[13];
    const float* beta  = (const float*)d_in[14];

    int N = in_sizes[0] / F;
    int E = in_sizes[2] / 2;

    float* xout = (float*)d_out;
    float* pout = (float*)d_out + (size_t)N * F;

    float* XA;   cudaGetSymbolAddress((void**)&XA,   g_XA);
    float* XB;   cudaGetSymbolAddress((void**)&XB,   g_XB);
    float* AGGS; cudaGetSymbolAddress((void**)&AGGS, g_AGGS);
    float* DEG;  cudaGetSymbolAddress((void**)&DEG,  g_DEG);

    cudaFuncSetAttribute(gemm_rt<0, 0>, cudaFuncAttributeMaxDynamicSharedMemorySize, SM_RT_TOTAL);
    cudaFuncSetAttribute(gemm_rt<1, 0>, cudaFuncAttributeMaxDynamicSharedMemorySize, SM_RT_TOTAL);
    cudaFuncSetAttribute(gemm_rt<0, 1>, cudaFuncAttributeMaxDynamicSharedMemorySize, SM_RT_TOTAL);

    int tcb = (N + 127) / 128;

    detect_kernel<<<1, 256>>>(ei, E, N);
    prep_vc<<<1, 128>>>(ew2, cw, eb2, cb);
    zero_kernel<<<2048, 256>>>(N);

    // XA = x @ W1a + eb1 AND XB = x @ W1b — one merged launch (R10 binary)
    gemm_rt<0, 0><<<dim3(tcb, 2), 256, SM_RT_TOTAL>>>(
        x, ew1, eb1, XA, ew1 + 128 * F, nullptr, XB,
        nullptr, nullptr, nullptr, nullptr, nullptr, N);

    // Edge stage
    int eblocks = (E * 32 + 255) / 256;
    edge_kernel<<<eblocks, 256>>>(ei, pos, ew1, E, N);

    // AGG = AGGS @ ew2 + deg*eb2  -> XA  (R10 binary)
    gemm_rt<0, 0><<<tcb, 256, SM_RT_TOTAL>>>(AGGS, ew2, nullptr, XA,
                                             nullptr, nullptr, nullptr,
                                             DEG, eb2, nullptr, nullptr, nullptr, N);
    // H = silu(AGG @ nw1 + nb1)   -> XB  (R10 binary)
    gemm_rt<1, 0><<<tcb, 256, SM_RT_TOTAL>>>(XA, nw1, nb1, XB,
                                             nullptr, nullptr, nullptr,
                                             nullptr, nullptr, nullptr, nullptr, nullptr, N);
    // x_out = LN(x + H @ nw2 + nb2) — dedicated fused instantiation
    gemm_rt<0, 1><<<tcb, 256, SM_RT_TOTAL>>>(XB, nw2, nb2, xout,
                                             nullptr, nullptr, nullptr,
                                             nullptr, nullptr, x, gamma, beta, N);
    // pos_out
    pos_kernel<<<(N * 3 + 255) / 256, 256>>>(pos, pout, N);
}

// round 14
// speedup vs baseline: 1.2749x; 1.0413x over previous
#include <cuda_runtime.h>
#include <cuda_bf16.h>
#include <math.h>
#include <stdint.h>

#define NMAX 50048
#define F 128
#define LN_EPS 1e-5f

// ---------------------------------------------------------------------------
// Scratch (device globals — no allocation allowed)
__device__ float g_XA[NMAX * F];
__device__ float g_XB[NMAX * F];
__device__ float g_AGGS[NMAX * F];
__device__ float g_DELTA[NMAX * 3];
__device__ float g_DEG[NMAX];
__device__ float g_V[F];
__device__ float g_VD[F];          // eb2 @ nw1
__device__ float g_M[F * F];       // ew2 @ nw1
__device__ float g_C0;
__device__ int   g_IS64;

// ---------------------------------------------------------------------------
#define FFMA2(acc, a, b) \
    asm("fma.rn.f32x2 %0, %1, %2, %0;" : "+l"(acc) : "l"(a), "l"(b))
__device__ __forceinline__ unsigned long long pack2(float v) {
    unsigned long long r;
    unsigned int u = __float_as_uint(v);
    asm("mov.b64 %0, {%1, %1};" : "=l"(r) : "r"(u));
    return r;
}
__device__ __forceinline__ void unpack2(unsigned long long p, float& lo, float& hi) {
    unsigned int a, b;
    asm("mov.b64 {%0, %1}, %2;" : "=r"(a), "=r"(b) : "l"(p));
    lo = __uint_as_float(a);
    hi = __uint_as_float(b);
}
__device__ __forceinline__ uint32_t smem_u32(const void* p) {
    uint32_t a;
    asm("{ .reg .u64 t; cvta.to.shared.u64 t, %1; cvt.u32.u64 %0, t; }"
        : "=r"(a) : "l"(p));
    return a;
}
#define CP_ASYNC16(dst, src) \
    asm volatile("cp.async.cg.shared.global [%0], [%1], 16;" :: "r"(dst), "l"(src))
#define CP_COMMIT() asm volatile("cp.async.commit_group;" ::: "memory")
#define CP_WAIT0()  asm volatile("cp.async.wait_group 0;" ::: "memory")

__device__ __forceinline__ float fast_sigmoid(float p) {
    return __fdividef(1.f, 1.f + __expf(-p));
}
__device__ __forceinline__ float fast_tanh(float x) {
    return 1.f - __fdividef(2.f, __expf(2.f * x) + 1.f);
}

// ---------------------------------------------------------------------------
__global__ void detect_kernel(const void* ei, int E, int N) {
    __shared__ int bad;
    if (threadIdx.x == 0) bad = 0;
    __syncthreads();
    int cnt = (2 * E < 256) ? 2 * E : 256;
    if ((int)threadIdx.x < cnt) {
        long long v = ((const long long*)ei)[threadIdx.x];
        if (v < 0 || v >= N) bad = 1;
    }
    __syncthreads();
    if (threadIdx.x == 0) g_IS64 = !bad;
}

// V = ew2 @ cw, C0 = eb2.cw + cb, VD = eb2 @ nw1
__global__ void prep_vc(const float* __restrict__ ew2, const float* __restrict__ cw,
                        const float* __restrict__ eb2, const float* __restrict__ cb,
                        const float* __restrict__ nw1) {
    int t = threadIdx.x;
    float s = 0.f;
    for (int o = 0; o < F; o++) s += ew2[t * F + o] * cw[o];
    g_V[t] = s;
    float vd = 0.f;
    for (int j = 0; j < F; j++) vd += eb2[j] * nw1[j * F + t];
    g_VD[t] = vd;
    if (t == 0) {
        float c = cb[0];
        for (int o = 0; o < F; o++) c += eb2[o] * cw[o];
        g_C0 = c;
    }
}

__global__ void zero_kernel(int N) {
    int n4 = N * 32;
    float4 z4 = make_float4(0.f, 0.f, 0.f, 0.f);
    float4* a4 = (float4*)g_AGGS;
    int stride = gridDim.x * blockDim.x;
    for (int i = blockIdx.x * blockDim.x + threadIdx.x; i < n4; i += stride) a4[i] = z4;
    for (int i = blockIdx.x * blockDim.x + threadIdx.x; i < N * 3; i += stride) g_DELTA[i] = 0.f;
    for (int i = blockIdx.x * blockDim.x + threadIdx.x; i < N; i += stride) g_DEG[i] = 0.f;
}

// ---------------------------------------------------------------------------
// Edge kernel: one warp per edge, v4 RED scatter (proven best structure).
__global__ void __launch_bounds__(256)
edge_kernel(const void* __restrict__ ei_raw, const float* __restrict__ pos,
            const float* __restrict__ ew1, int E, int N) {
    int gw = (blockIdx.x * blockDim.x + threadIdx.x) >> 5;
    int lane = threadIdx.x & 31;
    if (gw >= E) return;

    int row, col;
    if (g_IS64) {
        const long long* ei = (const long long*)ei_raw;
        row = (int)ei[gw];
        col = (int)ei[(size_t)E + gw];
    } else {
        const int* ei = (const int*)ei_raw;
        row = ei[gw];
        col = ei[E + gw];
    }

    float dx = pos[row * 3 + 0] - pos[col * 3 + 0];
    float dy = pos[row * 3 + 1] - pos[col * 3 + 1];
    float dz = pos[row * 3 + 2] - pos[col * 3 + 2];
    float dist2 = dx * dx + dy * dy + dz * dz;

    const float4* XA4 = (const float4*)g_XA;
    const float4* XB4 = (const float4*)g_XB;
    float4 a = XA4[(size_t)row * 32 + lane];
    float4 b = XB4[(size_t)col * 32 + lane];
    float4 w = __ldg((const float4*)(ew1 + 256 * F) + lane);

    float p0 = a.x + b.x + dist2 * w.x;
    float p1 = a.y + b.y + dist2 * w.y;
    float p2 = a.z + b.z + dist2 * w.z;
    float p3 = a.w + b.w + dist2 * w.w;

    float s0 = p0 * fast_sigmoid(p0);
    float s1 = p1 * fast_sigmoid(p1);
    float s2 = p2 * fast_sigmoid(p2);
    float s3 = p3 * fast_sigmoid(p3);

    float* aggp = g_AGGS + (size_t)row * F + lane * 4;
    asm volatile("red.global.add.v4.f32 [%0], {%1, %2, %3, %4};"
                 :: "l"(aggp), "f"(s0), "f"(s1), "f"(s2), "f"(s3) : "memory");

    float4 vv = ((const float4*)g_V)[lane];
    float d = s0 * vv.x + s1 * vv.y + s2 * vv.z + s3 * vv.w;
#pragma unroll
    for (int o = 16; o > 0; o >>= 1) d += __shfl_xor_sync(0xffffffffu, d, o);

    if (lane == 0) {
        float sc = fast_tanh(d + g_C0);
        atomicAdd(&g_DELTA[row * 3 + 0], sc * dx);
        atomicAdd(&g_DELTA[row * 3 + 1], sc * dy);
        atomicAdd(&g_DELTA[row * 3 + 2], sc * dz);
        atomicAdd(&g_DEG[row], 1.0f);
    }
}

// ---------------------------------------------------------------------------
// Pipelined register-tiled GEMM. LNFUSE compile-time: LNFUSE=0 == R10 binary.
#define AS_STRIDE 132
#define WS_BYTES  16384
#define AS_BYTES  16896
#define SM_AS0    (2 * WS_BYTES)
#define SM_RT_TOTAL (2 * WS_BYTES + 2 * AS_BYTES)

template <int ACT, int LNFUSE>
__global__ void __launch_bounds__(256, 2)
gemm_rt(const float* __restrict__ A,
        const float* __restrict__ W0, const float* __restrict__ bias0,
        float* __restrict__ out0,
        const float* __restrict__ W1, const float* __restrict__ bias1,
        float* __restrict__ out1,
        const float* __restrict__ deg, const float* __restrict__ degvec,
        const float* __restrict__ lnx, const float* __restrict__ gamma,
        const float* __restrict__ beta, int N) {
    extern __shared__ char smem[];

    const float* W = W0;
    const float* bias = bias0;
    float* out = out0;
    if (blockIdx.y == 1) { W = W1; bias = bias1; out = out1; }

    int t = threadIdx.x;
    int lane = t & 31, w = t >> 5;
    int txl = lane & 3, tyl = lane >> 2;
    int wx = w & 3, wy = w >> 2;
    int col0 = (wx * 4 + txl) * 8;
    int rowt = (wy * 8 + tyl) * 8;
    int row0 = blockIdx.x * 128;

    uint32_t sb = smem_u32(smem);

    int arl = (w & 3) * 32 + lane;
    int kh  = (w >> 2) * 16;
    int arow = row0 + arl;
    const float4* Abase = (const float4*)(A + (size_t)arow * F);

    int wk = t >> 3, wcol = (t & 7) * 16;

    unsigned long long acc[8][4];
#pragma unroll
    for (int r = 0; r < 8; r++)
#pragma unroll
        for (int c = 0; c < 4; c++) acc[r][c] = 0ull;

    float4 v[4];

    {
        const float* wsrc = W + (size_t)wk * F + wcol;
        uint32_t wdst = sb + (uint32_t)(wk * F + wcol) * 4;
#pragma unroll
        for (int q = 0; q < 4; q++) CP_ASYNC16(wdst + q * 16, wsrc + q * 4);
        CP_COMMIT();
        if (arow < N) {
#pragma unroll
            for (int q = 0; q < 4; q++) v[q] = __ldg(&Abase[(kh >> 2) + q]);
        } else {
#pragma unroll
            for (int q = 0; q < 4; q++) v[q] = make_float4(0.f, 0.f, 0.f, 0.f);
        }
        float* As0 = (float*)(smem + SM_AS0);
#pragma unroll
        for (int q = 0; q < 4; q++) {
            float vals[4] = {v[q].x, v[q].y, v[q].z, v[q].w};
#pragma unroll
            for (int e = 0; e < 4; e++)
                As0[(kh + q * 4 + e) * AS_STRIDE + arl] = vals[e];
        }
        CP_WAIT0();
    }
    __syncthreads();

#pragma unroll 1
    for (int c = 0; c < 4; c++) {
        int cb = c & 1, nb = (c + 1) & 1;
        float* Ws = (float*)(smem + cb * WS_BYTES);
        float* As = (float*)(smem + SM_AS0 + cb * AS_BYTES);

        if (c < 3) {
            const float* wsrc = W + (size_t)((c + 1) * 32 + wk) * F + wcol;
            uint32_t wdst = sb + (uint32_t)nb * WS_BYTES + (uint32_t)(wk * F + wcol) * 4;
#pragma unroll
            for (int q = 0; q < 4; q++) CP_ASYNC16(wdst + q * 16, wsrc + q * 4);
            CP_COMMIT();
            if (arow < N) {
                int kb = ((c + 1) * 32 + kh) >> 2;
#pragma unroll
                for (int q = 0; q < 4; q++) v[q] = __ldg(&Abase[kb + q]);
            }
        }

#pragma unroll
        for (int kk = 0; kk < 32; kk++) {
            float4 al = *(const float4*)&As[kk * AS_STRIDE + rowt];
            float4 ah = *(const float4*)&As[kk * AS_STRIDE + rowt + 4];
            unsigned long long a0 = pack2(al.x), a1 = pack2(al.y);
            unsigned long long a2 = pack2(al.z), a3 = pack2(al.w);
            unsigned long long a4 = pack2(ah.x), a5 = pack2(ah.y);
            unsigned long long a6 = pack2(ah.z), a7 = pack2(ah.w);
            ulonglong2 bv0 = *(const ulonglong2*)&Ws[kk * F + col0];
            ulonglong2 bv1 = *(const ulonglong2*)&Ws[kk * F + col0 + 4];
            FFMA2(acc[0][0], a0, bv0.x); FFMA2(acc[0][1], a0, bv0.y);
            FFMA2(acc[0][2], a0, bv1.x); FFMA2(acc[0][3], a0, bv1.y);
            FFMA2(acc[1][0], a1, bv0.x); FFMA2(acc[1][1], a1, bv0.y);
            FFMA2(acc[1][2], a1, bv1.x); FFMA2(acc[1][3], a1, bv1.y);
            FFMA2(acc[2][0], a2, bv0.x); FFMA2(acc[2][1], a2, bv0.y);
            FFMA2(acc[2][2], a2, bv1.x); FFMA2(acc[2][3], a2, bv1.y);
            FFMA2(acc[3][0], a3, bv0.x); FFMA2(acc[3][1], a3, bv0.y);
            FFMA2(acc[3][2], a3, bv1.x); FFMA2(acc[3][3], a3, bv1.y);
            FFMA2(acc[4][0], a4, bv0.x); FFMA2(acc[4][1], a4, bv0.y);
            FFMA2(acc[4][2], a4, bv1.x); FFMA2(acc[4][3], a4, bv1.y);
            FFMA2(acc[5][0], a5, bv0.x); FFMA2(acc[5][1], a5, bv0.y);
            FFMA2(acc[5][2], a5, bv1.x); FFMA2(acc[5][3], a5, bv1.y);
            FFMA2(acc[6][0], a6, bv0.x); FFMA2(acc[6][1], a6, bv0.y);
            FFMA2(acc[6][2], a6, bv1.x); FFMA2(acc[6][3], a6, bv1.y);
            FFMA2(acc[7][0], a7, bv0.x); FFMA2(acc[7][1], a7, bv0.y);
            FFMA2(acc[7][2], a7, bv1.x); FFMA2(acc[7][3], a7, bv1.y);
        }

        if (c < 3) {
            float* Asn = (float*)(smem + SM_AS0 + nb * AS_BYTES);
            if (arow >= N) {
#pragma unroll
                for (int q = 0; q < 4; q++) v[q] = make_float4(0.f, 0.f, 0.f, 0.f);
            }
#pragma unroll
            for (int q = 0; q < 4; q++) {
                float vals[4] = {v[q].x, v[q].y, v[q].z, v[q].w};
#pragma unroll
                for (int e = 0; e < 4; e++)
                    Asn[(kh + q * 4 + e) * AS_STRIDE + arl] = vals[e];
            }
            CP_WAIT0();
        }
        __syncthreads();
    }

    float bcol[8];
#pragma unroll
    for (int j = 0; j < 8; j++)
        bcol[j] = bias ? __ldg(&bias[col0 + j]) : 0.f;

    if (LNFUSE == 0) {
        float dcol[8];
#pragma unroll
        for (int j = 0; j < 8; j++)
            dcol[j] = degvec ? __ldg(&degvec[col0 + j]) : 0.f;
#pragma unroll
        for (int rr = 0; rr < 8; rr++) {
            int row = row0 + rowt + rr;
            if (row < N) {
                float dg = deg ? deg[row] : 0.f;
                float o[8];
#pragma unroll
                for (int cp = 0; cp < 4; cp++) unpack2(acc[rr][cp], o[2 * cp], o[2 * cp + 1]);
#pragma unroll
                for (int j = 0; j < 8; j++) {
                    float vv2 = o[j] + bcol[j] + dg * dcol[j];
                    if (ACT == 1) vv2 = vv2 * fast_sigmoid(vv2);
                    o[j] = vv2;
                }
                float4* op = (float4*)(out + (size_t)row * F + col0);
                op[0] = make_float4(o[0], o[1], o[2], o[3]);
                op[1] = make_float4(o[4], o[5], o[6], o[7]);
            }
        }
    } else {
        // Fused residual + LayerNorm epilogue.
        float* part = (float*)smem;
        float* smu = (float*)(smem + 16384);
        float* sri = (float*)(smem + 16896);
        int cg = wx * 4 + txl;

#pragma unroll
        for (int rr = 0; rr < 8; rr++) {
            int row = row0 + rowt + rr;
            float s = 0.f, s2 = 0.f;
            if (row < N) {
                float o[8];
#pragma unroll
                for (int cp = 0; cp < 4; cp++) unpack2(acc[rr][cp], o[2 * cp], o[2 * cp + 1]);
                const float4* xp = (const float4*)(lnx + (size_t)row * F + col0);
                float4 x0 = __ldg(&xp[0]), x1 = __ldg(&xp[1]);
                float xv[8] = {x0.x, x0.y, x0.z, x0.w, x1.x, x1.y, x1.z, x1.w};
#pragma unroll
                for (int j = 0; j < 8; j++) {
                    float p = o[j] + bcol[j] + xv[j];
                    s += p;
                    s2 += p * p;
                }
            }
            part[((rowt + rr) * 16 + cg) * 2 + 0] = s;
            part[((rowt + rr) * 16 + cg) * 2 + 1] = s2;
        }
        __syncthreads();

        {
            int row = t >> 1, half = t & 1;
            float s = 0.f, s2 = 0.f;
#pragma unroll
            for (int q = 0; q < 8; q++) {
                s  += part[(row * 16 + half * 8 + q) * 2 + 0];
                s2 += part[(row * 16 + half * 8 + q) * 2 + 1];
            }
            s  += __shfl_xor_sync(0xffffffffu, s, 1);
            s2 += __shfl_xor_sync(0xffffffffu, s2, 1);
            if (half == 0) {
                float mean = s * (1.f / F);
                smu[row] = mean;
                sri[row] = rsqrtf(s2 * (1.f / F) - mean * mean + LN_EPS);
            }
        }
        __syncthreads();

        float gcol[8], becol[8];
#pragma unroll
        for (int j = 0; j < 8; j++) {
            gcol[j]  = __ldg(&gamma[col0 + j]);
            becol[j] = __ldg(&beta[col0 + j]);
        }
#pragma unroll
        for (int rr = 0; rr < 8; rr++) {
            int row = row0 + rowt + rr;
            if (row < N) {
                float mu = smu[rowt + rr];
                float ri = sri[rowt + rr];
                float o[8];
#pragma unroll
                for (int cp = 0; cp < 4; cp++) unpack2(acc[rr][cp], o[2 * cp], o[2 * cp + 1]);
                const float4* xp = (const float4*)(lnx + (size_t)row * F + col0);
                float4 x0 = __ldg(&xp[0]), x1 = __ldg(&xp[1]);
                float xv[8] = {x0.x, x0.y, x0.z, x0.w, x1.x, x1.y, x1.z, x1.w};
#pragma unroll
                for (int j = 0; j < 8; j++) {
                    float p = o[j] + bcol[j] + xv[j];
                    o[j] = gcol[j] * (p - mu) * ri + becol[j];
                }
                float4* op = (float4*)(out + (size_t)row * F + col0);
                op[0] = make_float4(o[0], o[1], o[2], o[3]);
                op[1] = make_float4(o[4], o[5], o[6], o[7]);
            }
        }
    }
}

// ---------------------------------------------------------------------------
__global__ void pos_kernel(const float* __restrict__ pos, float* __restrict__ out, int N) {
    int i = blockIdx.x * blockDim.x + threadIdx.x;
    if (i < N * 3) out[i] = pos[i] + g_DELTA[i];
}

// ---------------------------------------------------------------------------
extern "C" void kernel_launch(void* const* d_in, const int* in_sizes, int n_in,
                              void* d_out, int out_size) {
    const float* x     = (const float*)d_in[0];
    const float* pos   = (const float*)d_in[1];
    const void*  ei    = d_in[2];
    const float* ew1   = (const float*)d_in[3];
    const float* eb1   = (const float*)d_in[4];
    const float* ew2   = (const float*)d_in[5];
    const float* eb2   = (const float*)d_in[6];
    const float* nw1   = (const float*)d_in[7];
    const float* nb1   = (const float*)d_in[8];
    const float* nw2   = (const float*)d_in[9];
    const float* nb2   = (const float*)d_in[10];
    const float* cw    = (const float*)d_in[11];
    const float* cb    = (const float*)d_in[12];
    const float* gamma = (const float*)d_in[13];
    const float* beta  = (const float*)d_in[14];

    int N = in_sizes[0] / F;
    int E = in_sizes[2] / 2;

    float* xout = (float*)d_out;
    float* pout = (float*)d_out + (size_t)N * F;

    float* XA;   cudaGetSymbolAddress((void**)&XA,   g_XA);
    float* XB;   cudaGetSymbolAddress((void**)&XB,   g_XB);
    float* AGGS; cudaGetSymbolAddress((void**)&AGGS, g_AGGS);
    float* DEG;  cudaGetSymbolAddress((void**)&DEG,  g_DEG);
    float* VD;   cudaGetSymbolAddress((void**)&VD,   g_VD);
    float* M;    cudaGetSymbolAddress((void**)&M,    g_M);

    cudaFuncSetAttribute(gemm_rt<0, 0>, cudaFuncAttributeMaxDynamicSharedMemorySize, SM_RT_TOTAL);
    cudaFuncSetAttribute(gemm_rt<1, 0>, cudaFuncAttributeMaxDynamicSharedMemorySize, SM_RT_TOTAL);
    cudaFuncSetAttribute(gemm_rt<0, 1>, cudaFuncAttributeMaxDynamicSharedMemorySize, SM_RT_TOTAL);

    int tcb = (N + 127) / 128;

    detect_kernel<<<1, 256>>>(ei, E, N);
    prep_vc<<<1, 128>>>(ew2, cw, eb2, cb, nw1);
    zero_kernel<<<2048, 256>>>(N);

    // M = ew2 @ nw1 — single-block GEMM (fuses away the AGG GEMM)
    gemm_rt<0, 0><<<1, 256, SM_RT_TOTAL>>>(
        ew2, nw1, nullptr, M, nullptr, nullptr, nullptr,
        nullptr, nullptr, nullptr, nullptr, nullptr, F);

    // XA = x @ W1a + eb1 AND XB = x @ W1b — merged dual launch (R10 binary)
    gemm_rt<0, 0><<<dim3(tcb, 2), 256, SM_RT_TOTAL>>>(
        x, ew1, eb1, XA, ew1 + 128 * F, nullptr, XB,
        nullptr, nullptr, nullptr, nullptr, nullptr, N);

    // Edge stage
    int eblocks = (E * 32 + 255) / 256;
    edge_kernel<<<eblocks, 256>>>(ei, pos, ew1, E, N);

    // H = silu(AGGS @ M + deg*VD + nb1) -> XB   (AGG GEMM algebraically folded)
    gemm_rt<1, 0><<<tcb, 256, SM_RT_TOTAL>>>(AGGS, M, nb1, XB,
                                             nullptr, nullptr, nullptr,
                                             DEG, VD, nullptr, nullptr, nullptr, N);
    // x_out = LN(x + H @ nw2 + nb2) — fused instantiation
    gemm_rt<0, 1><<<tcb, 256, SM_RT_TOTAL>>>(XB, nw2, nb2, xout,
                                             nullptr, nullptr, nullptr,
                                             nullptr, nullptr, x, gamma, beta, N);
    // pos_out
    pos_kernel<<<(N * 3 + 255) / 256, 256>>>(pos, pout, N);
}

// round 15
// speedup vs baseline: 1.3174x; 1.0334x over previous
#include <cuda_runtime.h>
#include <cuda_bf16.h>
#include <math.h>
#include <stdint.h>

#define NMAX 50048
#define F 128
#define LN_EPS 1e-5f

// ---------------------------------------------------------------------------
// Scratch (device globals — no allocation allowed)
__device__ float g_XA[NMAX * F];
__device__ float g_XB[NMAX * F];
__device__ float g_AGGS[NMAX * F];
__device__ float g_DELTA[NMAX * 3];
__device__ float g_DEG[NMAX];
__device__ float g_V[F];
__device__ float g_VD[F];          // eb2 @ nw1
__device__ float g_M[F * F];       // ew2 @ nw1
__device__ float g_C0;
__device__ int   g_IS64;

// ---------------------------------------------------------------------------
#define FFMA2(acc, a, b) \
    asm("fma.rn.f32x2 %0, %1, %2, %0;" : "+l"(acc) : "l"(a), "l"(b))
__device__ __forceinline__ unsigned long long pack2(float v) {
    unsigned long long r;
    unsigned int u = __float_as_uint(v);
    asm("mov.b64 %0, {%1, %1};" : "=l"(r) : "r"(u));
    return r;
}
__device__ __forceinline__ void unpack2(unsigned long long p, float& lo, float& hi) {
    unsigned int a, b;
    asm("mov.b64 {%0, %1}, %2;" : "=r"(a), "=r"(b) : "l"(p));
    lo = __uint_as_float(a);
    hi = __uint_as_float(b);
}
__device__ __forceinline__ uint32_t smem_u32(const void* p) {
    uint32_t a;
    asm("{ .reg .u64 t; cvta.to.shared.u64 t, %1; cvt.u32.u64 %0, t; }"
        : "=r"(a) : "l"(p));
    return a;
}
#define CP_ASYNC16(dst, src) \
    asm volatile("cp.async.cg.shared.global [%0], [%1], 16;" :: "r"(dst), "l"(src))
#define CP_COMMIT() asm volatile("cp.async.commit_group;" ::: "memory")
#define CP_WAIT0()  asm volatile("cp.async.wait_group 0;" ::: "memory")

__device__ __forceinline__ float fast_sigmoid(float p) {
    return __fdividef(1.f, 1.f + __expf(-p));
}
__device__ __forceinline__ float fast_tanh(float x) {
    return 1.f - __fdividef(2.f, __expf(2.f * x) + 1.f);
}

// ---------------------------------------------------------------------------
__global__ void detect_kernel(const void* ei, int E, int N) {
    __shared__ int bad;
    if (threadIdx.x == 0) bad = 0;
    __syncthreads();
    int cnt = (2 * E < 256) ? 2 * E : 256;
    if ((int)threadIdx.x < cnt) {
        long long v = ((const long long*)ei)[threadIdx.x];
        if (v < 0 || v >= N) bad = 1;
    }
    __syncthreads();
    if (threadIdx.x == 0) g_IS64 = !bad;
}

// V = ew2 @ cw, C0 = eb2.cw + cb, VD = eb2 @ nw1
__global__ void prep_vc(const float* __restrict__ ew2, const float* __restrict__ cw,
                        const float* __restrict__ eb2, const float* __restrict__ cb,
                        const float* __restrict__ nw1) {
    int t = threadIdx.x;
    float s = 0.f;
    for (int o = 0; o < F; o++) s += ew2[t * F + o] * cw[o];
    g_V[t] = s;
    float vd = 0.f;
    for (int j = 0; j < F; j++) vd += eb2[j] * nw1[j * F + t];
    g_VD[t] = vd;
    if (t == 0) {
        float c = cb[0];
        for (int o = 0; o < F; o++) c += eb2[o] * cw[o];
        g_C0 = c;
    }
}

// Parallel M = ew2 @ nw1: 64 blocks x 256 threads, one element per thread.
__global__ void __launch_bounds__(256)
prep_m(const float* __restrict__ ew2, const float* __restrict__ nw1) {
    int gid = blockIdx.x * 256 + threadIdx.x;   // 0..16383
    int r = gid >> 7, c = gid & 127;
    float acc = 0.f;
#pragma unroll 8
    for (int k = 0; k < F; k++)
        acc += __ldg(&ew2[r * F + k]) * __ldg(&nw1[k * F + c]);
    g_M[gid] = acc;
}

__global__ void zero_kernel(int N) {
    int n4 = N * 32;
    float4 z4 = make_float4(0.f, 0.f, 0.f, 0.f);
    float4* a4 = (float4*)g_AGGS;
    int stride = gridDim.x * blockDim.x;
    for (int i = blockIdx.x * blockDim.x + threadIdx.x; i < n4; i += stride) a4[i] = z4;
    for (int i = blockIdx.x * blockDim.x + threadIdx.x; i < N * 3; i += stride) g_DELTA[i] = 0.f;
    for (int i = blockIdx.x * blockDim.x + threadIdx.x; i < N; i += stride) g_DEG[i] = 0.f;
}

// ---------------------------------------------------------------------------
// Edge kernel: one warp per edge, v4 RED scatter (proven best structure).
__global__ void __launch_bounds__(256)
edge_kernel(const void* __restrict__ ei_raw, const float* __restrict__ pos,
            const float* __restrict__ ew1, int E, int N) {
    int gw = (blockIdx.x * blockDim.x + threadIdx.x) >> 5;
    int lane = threadIdx.x & 31;
    if (gw >= E) return;

    int row, col;
    if (g_IS64) {
        const long long* ei = (const long long*)ei_raw;
        row = (int)ei[gw];
        col = (int)ei[(size_t)E + gw];
    } else {
        const int* ei = (const int*)ei_raw;
        row = ei[gw];
        col = ei[E + gw];
    }

    float dx = pos[row * 3 + 0] - pos[col * 3 + 0];
    float dy = pos[row * 3 + 1] - pos[col * 3 + 1];
    float dz = pos[row * 3 + 2] - pos[col * 3 + 2];
    float dist2 = dx * dx + dy * dy + dz * dz;

    const float4* XA4 = (const float4*)g_XA;
    const float4* XB4 = (const float4*)g_XB;
    float4 a = XA4[(size_t)row * 32 + lane];
    float4 b = XB4[(size_t)col * 32 + lane];
    float4 w = __ldg((const float4*)(ew1 + 256 * F) + lane);

    float p0 = a.x + b.x + dist2 * w.x;
    float p1 = a.y + b.y + dist2 * w.y;
    float p2 = a.z + b.z + dist2 * w.z;
    float p3 = a.w + b.w + dist2 * w.w;

    float s0 = p0 * fast_sigmoid(p0);
    float s1 = p1 * fast_sigmoid(p1);
    float s2 = p2 * fast_sigmoid(p2);
    float s3 = p3 * fast_sigmoid(p3);

    float* aggp = g_AGGS + (size_t)row * F + lane * 4;
    asm volatile("red.global.add.v4.f32 [%0], {%1, %2, %3, %4};"
                 :: "l"(aggp), "f"(s0), "f"(s1), "f"(s2), "f"(s3) : "memory");

    float4 vv = ((const float4*)g_V)[lane];
    float d = s0 * vv.x + s1 * vv.y + s2 * vv.z + s3 * vv.w;
#pragma unroll
    for (int o = 16; o > 0; o >>= 1) d += __shfl_xor_sync(0xffffffffu, d, o);

    if (lane == 0) {
        float sc = fast_tanh(d + g_C0);
        atomicAdd(&g_DELTA[row * 3 + 0], sc * dx);
        atomicAdd(&g_DELTA[row * 3 + 1], sc * dy);
        atomicAdd(&g_DELTA[row * 3 + 2], sc * dz);
        atomicAdd(&g_DEG[row], 1.0f);
    }
}

// ---------------------------------------------------------------------------
// Pipelined register-tiled GEMM. LNFUSE compile-time: LNFUSE=0 == R10 binary.
#define AS_STRIDE 132
#define WS_BYTES  16384
#define AS_BYTES  16896
#define SM_AS0    (2 * WS_BYTES)
#define SM_RT_TOTAL (2 * WS_BYTES + 2 * AS_BYTES)

template <int ACT, int LNFUSE>
__global__ void __launch_bounds__(256, 2)
gemm_rt(const float* __restrict__ A,
        const float* __restrict__ W0, const float* __restrict__ bias0,
        float* __restrict__ out0,
        const float* __restrict__ W1, const float* __restrict__ bias1,
        float* __restrict__ out1,
        const float* __restrict__ deg, const float* __restrict__ degvec,
        const float* __restrict__ lnx, const float* __restrict__ gamma,
        const float* __restrict__ beta, int N) {
    extern __shared__ char smem[];

    const float* W = W0;
    const float* bias = bias0;
    float* out = out0;
    if (blockIdx.y == 1) { W = W1; bias = bias1; out = out1; }

    int t = threadIdx.x;
    int lane = t & 31, w = t >> 5;
    int txl = lane & 3, tyl = lane >> 2;
    int wx = w & 3, wy = w >> 2;
    int col0 = (wx * 4 + txl) * 8;
    int rowt = (wy * 8 + tyl) * 8;
    int row0 = blockIdx.x * 128;

    uint32_t sb = smem_u32(smem);

    int arl = (w & 3) * 32 + lane;
    int kh  = (w >> 2) * 16;
    int arow = row0 + arl;
    const float4* Abase = (const float4*)(A + (size_t)arow * F);

    int wk = t >> 3, wcol = (t & 7) * 16;

    unsigned long long acc[8][4];
#pragma unroll
    for (int r = 0; r < 8; r++)
#pragma unroll
        for (int c = 0; c < 4; c++) acc[r][c] = 0ull;

    float4 v[4];

    {
        const float* wsrc = W + (size_t)wk * F + wcol;
        uint32_t wdst = sb + (uint32_t)(wk * F + wcol) * 4;
#pragma unroll
        for (int q = 0; q < 4; q++) CP_ASYNC16(wdst + q * 16, wsrc + q * 4);
        CP_COMMIT();
        if (arow < N) {
#pragma unroll
            for (int q = 0; q < 4; q++) v[q] = __ldg(&Abase[(kh >> 2) + q]);
        } else {
#pragma unroll
            for (int q = 0; q < 4; q++) v[q] = make_float4(0.f, 0.f, 0.f, 0.f);
        }
        float* As0 = (float*)(smem + SM_AS0);
#pragma unroll
        for (int q = 0; q < 4; q++) {
            float vals[4] = {v[q].x, v[q].y, v[q].z, v[q].w};
#pragma unroll
            for (int e = 0; e < 4; e++)
                As0[(kh + q * 4 + e) * AS_STRIDE + arl] = vals[e];
        }
        CP_WAIT0();
    }
    __syncthreads();

#pragma unroll 1
    for (int c = 0; c < 4; c++) {
        int cb = c & 1, nb = (c + 1) & 1;
        float* Ws = (float*)(smem + cb * WS_BYTES);
        float* As = (float*)(smem + SM_AS0 + cb * AS_BYTES);

        if (c < 3) {
            const float* wsrc = W + (size_t)((c + 1) * 32 + wk) * F + wcol;
            uint32_t wdst = sb + (uint32_t)nb * WS_BYTES + (uint32_t)(wk * F + wcol) * 4;
#pragma unroll
            for (int q = 0; q < 4; q++) CP_ASYNC16(wdst + q * 16, wsrc + q * 4);
            CP_COMMIT();
            if (arow < N) {
                int kb = ((c + 1) * 32 + kh) >> 2;
#pragma unroll
                for (int q = 0; q < 4; q++) v[q] = __ldg(&Abase[kb + q]);
            }
        }

#pragma unroll
        for (int kk = 0; kk < 32; kk++) {
            float4 al = *(const float4*)&As[kk * AS_STRIDE + rowt];
            float4 ah = *(const float4*)&As[kk * AS_STRIDE + rowt + 4];
            unsigned long long a0 = pack2(al.x), a1 = pack2(al.y);
            unsigned long long a2 = pack2(al.z), a3 = pack2(al.w);
            unsigned long long a4 = pack2(ah.x), a5 = pack2(ah.y);
            unsigned long long a6 = pack2(ah.z), a7 = pack2(ah.w);
            ulonglong2 bv0 = *(const ulonglong2*)&Ws[kk * F + col0];
            ulonglong2 bv1 = *(const ulonglong2*)&Ws[kk * F + col0 + 4];
            FFMA2(acc[0][0], a0, bv0.x); FFMA2(acc[0][1], a0, bv0.y);
            FFMA2(acc[0][2], a0, bv1.x); FFMA2(acc[0][3], a0, bv1.y);
            FFMA2(acc[1][0], a1, bv0.x); FFMA2(acc[1][1], a1, bv0.y);
            FFMA2(acc[1][2], a1, bv1.x); FFMA2(acc[1][3], a1, bv1.y);
            FFMA2(acc[2][0], a2, bv0.x); FFMA2(acc[2][1], a2, bv0.y);
            FFMA2(acc[2][2], a2, bv1.x); FFMA2(acc[2][3], a2, bv1.y);
            FFMA2(acc[3][0], a3, bv0.x); FFMA2(acc[3][1], a3, bv0.y);
            FFMA2(acc[3][2], a3, bv1.x); FFMA2(acc[3][3], a3, bv1.y);
            FFMA2(acc[4][0], a4, bv0.x); FFMA2(acc[4][1], a4, bv0.y);
            FFMA2(acc[4][2], a4, bv1.x); FFMA2(acc[4][3], a4, bv1.y);
            FFMA2(acc[5][0], a5, bv0.x); FFMA2(acc[5][1], a5, bv0.y);
            FFMA2(acc[5][2], a5, bv1.x); FFMA2(acc[5][3], a5, bv1.y);
            FFMA2(acc[6][0], a6, bv0.x); FFMA2(acc[6][1], a6, bv0.y);
            FFMA2(acc[6][2], a6, bv1.x); FFMA2(acc[6][3], a6, bv1.y);
            FFMA2(acc[7][0], a7, bv0.x); FFMA2(acc[7][1], a7, bv0.y);
            FFMA2(acc[7][2], a7, bv1.x); FFMA2(acc[7][3], a7, bv1.y);
        }

        if (c < 3) {
            float* Asn = (float*)(smem + SM_AS0 + nb * AS_BYTES);
            if (arow >= N) {
#pragma unroll
                for (int q = 0; q < 4; q++) v[q] = make_float4(0.f, 0.f, 0.f, 0.f);
            }
#pragma unroll
            for (int q = 0; q < 4; q++) {
                float vals[4] = {v[q].x, v[q].y, v[q].z, v[q].w};
#pragma unroll
                for (int e = 0; e < 4; e++)
                    Asn[(kh + q * 4 + e) * AS_STRIDE + arl] = vals[e];
            }
            CP_WAIT0();
        }
        __syncthreads();
    }

    float bcol[8];
#pragma unroll
    for (int j = 0; j < 8; j++)
        bcol[j] = bias ? __ldg(&bias[col0 + j]) : 0.f;

    if (LNFUSE == 0) {
        float dcol[8];
#pragma unroll
        for (int j = 0; j < 8; j++)
            dcol[j] = degvec ? __ldg(&degvec[col0 + j]) : 0.f;
#pragma unroll
        for (int rr = 0; rr < 8; rr++) {
            int row = row0 + rowt + rr;
            if (row < N) {
                float dg = deg ? deg[row] : 0.f;
                float o[8];
#pragma unroll
                for (int cp = 0; cp < 4; cp++) unpack2(acc[rr][cp], o[2 * cp], o[2 * cp + 1]);
#pragma unroll
                for (int j = 0; j < 8; j++) {
                    float vv2 = o[j] + bcol[j] + dg * dcol[j];
                    if (ACT == 1) vv2 = vv2 * fast_sigmoid(vv2);
                    o[j] = vv2;
                }
                float4* op = (float4*)(out + (size_t)row * F + col0);
                op[0] = make_float4(o[0], o[1], o[2], o[3]);
                op[1] = make_float4(o[4], o[5], o[6], o[7]);
            }
        }
    } else {
        // Fused residual + LayerNorm epilogue.
        float* part = (float*)smem;
        float* smu = (float*)(smem + 16384);
        float* sri = (float*)(smem + 16896);
        int cg = wx * 4 + txl;

#pragma unroll
        for (int rr = 0; rr < 8; rr++) {
            int row = row0 + rowt + rr;
            float s = 0.f, s2 = 0.f;
            if (row < N) {
                float o[8];
#pragma unroll
                for (int cp = 0; cp < 4; cp++) unpack2(acc[rr][cp], o[2 * cp], o[2 * cp + 1]);
                const float4* xp = (const float4*)(lnx + (size_t)row * F + col0);
                float4 x0 = __ldg(&xp[0]), x1 = __ldg(&xp[1]);
                float xv[8] = {x0.x, x0.y, x0.z, x0.w, x1.x, x1.y, x1.z, x1.w};
#pragma unroll
                for (int j = 0; j < 8; j++) {
                    float p = o[j] + bcol[j] + xv[j];
                    s += p;
                    s2 += p * p;
                }
            }
            part[((rowt + rr) * 16 + cg) * 2 + 0] = s;
            part[((rowt + rr) * 16 + cg) * 2 + 1] = s2;
        }
        __syncthreads();

        {
            int row = t >> 1, half = t & 1;
            float s = 0.f, s2 = 0.f;
#pragma unroll
            for (int q = 0; q < 8; q++) {
                s  += part[(row * 16 + half * 8 + q) * 2 + 0];
                s2 += part[(row * 16 + half * 8 + q) * 2 + 1];
            }
            s  += __shfl_xor_sync(0xffffffffu, s, 1);
            s2 += __shfl_xor_sync(0xffffffffu, s2, 1);
            if (half == 0) {
                float mean = s * (1.f / F);
                smu[row] = mean;
                sri[row] = rsqrtf(s2 * (1.f / F) - mean * mean + LN_EPS);
            }
        }
        __syncthreads();

        float gcol[8], becol[8];
#pragma unroll
        for (int j = 0; j < 8; j++) {
            gcol[j]  = __ldg(&gamma[col0 + j]);
            becol[j] = __ldg(&beta[col0 + j]);
        }
#pragma unroll
        for (int rr = 0; rr < 8; rr++) {
            int row = row0 + rowt + rr;
            if (row < N) {
                float mu = smu[rowt + rr];
                float ri = sri[rowt + rr];
                float o[8];
#pragma unroll
                for (int cp = 0; cp < 4; cp++) unpack2(acc[rr][cp], o[2 * cp], o[2 * cp + 1]);
                const float4* xp = (const float4*)(lnx + (size_t)row * F + col0);
                float4 x0 = __ldg(&xp[0]), x1 = __ldg(&xp[1]);
                float xv[8] = {x0.x, x0.y, x0.z, x0.w, x1.x, x1.y, x1.z, x1.w};
#pragma unroll
                for (int j = 0; j < 8; j++) {
                    float p = o[j] + bcol[j] + xv[j];
                    o[j] = gcol[j] * (p - mu) * ri + becol[j];
                }
                float4* op = (float4*)(out + (size_t)row * F + col0);
                op[0] = make_float4(o[0], o[1], o[2], o[3]);
                op[1] = make_float4(o[4], o[5], o[6], o[7]);
            }
        }
    }
}

// ---------------------------------------------------------------------------
__global__ void pos_kernel(const float* __restrict__ pos, float* __restrict__ out, int N) {
    int i = blockIdx.x * blockDim.x + threadIdx.x;
    if (i < N * 3) out[i] = pos[i] + g_DELTA[i];
}

// ---------------------------------------------------------------------------
extern "C" void kernel_launch(void* const* d_in, const int* in_sizes, int n_in,
                              void* d_out, int out_size) {
    const float* x     = (const float*)d_in[0];
    const float* pos   = (const float*)d_in[1];
    const void*  ei    = d_in[2];
    const float* ew1   = (const float*)d_in[3];
    const float* eb1   = (const float*)d_in[4];
    const float* ew2   = (const float*)d_in[5];
    const float* eb2   = (const float*)d_in[6];
    const float* nw1   = (const float*)d_in[7];
    const float* nb1   = (const float*)d_in[8];
    const float* nw2   = (const float*)d_in[9];
    const float* nb2   = (const float*)d_in[10];
    const float* cw    = (const float*)d_in[11];
    const float* cb    = (const float*)d_in[12];
    const float* gamma = (const float*)d_in[13];
    const float* beta  = (const float*)d_in[14];

    int N = in_sizes[0] / F;
    int E = in_sizes[2] / 2;

    float* xout = (float*)d_out;
    float* pout = (float*)d_out + (size_t)N * F;

    float* XA;   cudaGetSymbolAddress((void**)&XA,   g_XA);
    float* XB;   cudaGetSymbolAddress((void**)&XB,   g_XB);
    float* AGGS; cudaGetSymbolAddress((void**)&AGGS, g_AGGS);
    float* DEG;  cudaGetSymbolAddress((void**)&DEG,  g_DEG);
    float* VD;   cudaGetSymbolAddress((void**)&VD,   g_VD);
    float* M;    cudaGetSymbolAddress((void**)&M,    g_M);

    cudaFuncSetAttribute(gemm_rt<0, 0>, cudaFuncAttributeMaxDynamicSharedMemorySize, SM_RT_TOTAL);
    cudaFuncSetAttribute(gemm_rt<1, 0>, cudaFuncAttributeMaxDynamicSharedMemorySize, SM_RT_TOTAL);
    cudaFuncSetAttribute(gemm_rt<0, 1>, cudaFuncAttributeMaxDynamicSharedMemorySize, SM_RT_TOTAL);

    int tcb = (N + 127) / 128;

    detect_kernel<<<1, 256>>>(ei, E, N);
    prep_vc<<<1, 128>>>(ew2, cw, eb2, cb, nw1);
    prep_m<<<64, 256>>>(ew2, nw1);
    zero_kernel<<<2048, 256>>>(N);

    // XA = x @ W1a + eb1 AND XB = x @ W1b — merged dual launch (R10 binary)
    gemm_rt<0, 0><<<dim3(tcb, 2), 256, SM_RT_TOTAL>>>(
        x, ew1, eb1, XA, ew1 + 128 * F, nullptr, XB,
        nullptr, nullptr, nullptr, nullptr, nullptr, N);

    // Edge stage
    int eblocks = (E * 32 + 255) / 256;
    edge_kernel<<<eblocks, 256>>>(ei, pos, ew1, E, N);

    // H = silu(AGGS @ M + deg*VD + nb1) -> XB   (AGG GEMM algebraically folded)
    gemm_rt<1, 0><<<tcb, 256, SM_RT_TOTAL>>>(AGGS, M, nb1, XB,
                                             nullptr, nullptr, nullptr,
                                             DEG, VD, nullptr, nullptr, nullptr, N);
    // x_out = LN(x + H @ nw2 + nb2) — fused instantiation
    gemm_rt<0, 1><<<tcb, 256, SM_RT_TOTAL>>>(XB, nw2, nb2, xout,
                                             nullptr, nullptr, nullptr,
                                             nullptr, nullptr, x, gamma, beta, N);
    // pos_out
    pos_kernel<<<(N * 3 + 255) / 256, 256>>>(pos, pout, N);
}

// round 16
// speedup vs baseline: 1.3431x; 1.0194x over previous
#include <cuda_runtime.h>
#include <cuda_bf16.h>
#include <cuda_fp16.h>
#include <math.h>
#include <stdint.h>

#define NMAX 50048
#define F 128
#define LN_EPS 1e-5f

// ---------------------------------------------------------------------------
// Scratch (device globals — no allocation allowed)
__device__ __half g_XAh[NMAX * F];   // fp16 x@W1a+eb1 (edge-kernel feed)
__device__ __half g_XBh[NMAX * F];   // fp16 x@W1b
__device__ float g_XB[NMAX * F];     // fp32 H (node MLP hidden)
__device__ float g_AGGS[NMAX * F];
__device__ float g_DELTA[NMAX * 3];
__device__ float g_DEG[NMAX];
__device__ float g_V[F];
__device__ float g_VD[F];            // eb2 @ nw1
__device__ float g_M[F * F];         // ew2 @ nw1
__device__ float g_C0;
__device__ int   g_IS64;

// ---------------------------------------------------------------------------
#define FFMA2(acc, a, b) \
    asm("fma.rn.f32x2 %0, %1, %2, %0;" : "+l"(acc) : "l"(a), "l"(b))
__device__ __forceinline__ unsigned long long pack2(float v) {
    unsigned long long r;
    unsigned int u = __float_as_uint(v);
    asm("mov.b64 %0, {%1, %1};" : "=l"(r) : "r"(u));
    return r;
}
__device__ __forceinline__ void unpack2(unsigned long long p, float& lo, float& hi) {
    unsigned int a, b;
    asm("mov.b64 {%0, %1}, %2;" : "=r"(a), "=r"(b) : "l"(p));
    lo = __uint_as_float(a);
    hi = __uint_as_float(b);
}
__device__ __forceinline__ uint32_t smem_u32(const void* p) {
    uint32_t a;
    asm("{ .reg .u64 t; cvta.to.shared.u64 t, %1; cvt.u32.u64 %0, t; }"
        : "=r"(a) : "l"(p));
    return a;
}
#define CP_ASYNC16(dst, src) \
    asm volatile("cp.async.cg.shared.global [%0], [%1], 16;" :: "r"(dst), "l"(src))
#define CP_COMMIT() asm volatile("cp.async.commit_group;" ::: "memory")
#define CP_WAIT0()  asm volatile("cp.async.wait_group 0;" ::: "memory")

__device__ __forceinline__ float fast_sigmoid(float p) {
    return __fdividef(1.f, 1.f + __expf(-p));
}
__device__ __forceinline__ float fast_tanh(float x) {
    return 1.f - __fdividef(2.f, __expf(2.f * x) + 1.f);
}

// ---------------------------------------------------------------------------
__global__ void detect_kernel(const void* ei, int E, int N) {
    __shared__ int bad;
    if (threadIdx.x == 0) bad = 0;
    __syncthreads();
    int cnt = (2 * E < 256) ? 2 * E : 256;
    if ((int)threadIdx.x < cnt) {
        long long v = ((const long long*)ei)[threadIdx.x];
        if (v < 0 || v >= N) bad = 1;
    }
    __syncthreads();
    if (threadIdx.x == 0) g_IS64 = !bad;
}

// V = ew2 @ cw, C0 = eb2.cw + cb, VD = eb2 @ nw1
__global__ void prep_vc(const float* __restrict__ ew2, const float* __restrict__ cw,
                        const float* __restrict__ eb2, const float* __restrict__ cb,
                        const float* __restrict__ nw1) {
    int t = threadIdx.x;
    float s = 0.f;
    for (int o = 0; o < F; o++) s += ew2[t * F + o] * cw[o];
    g_V[t] = s;
    float vd = 0.f;
    for (int j = 0; j < F; j++) vd += eb2[j] * nw1[j * F + t];
    g_VD[t] = vd;
    if (t == 0) {
        float c = cb[0];
        for (int o = 0; o < F; o++) c += eb2[o] * cw[o];
        g_C0 = c;
    }
}

// Parallel M = ew2 @ nw1
__global__ void __launch_bounds__(256)
prep_m(const float* __restrict__ ew2, const float* __restrict__ nw1) {
    int gid = blockIdx.x * 256 + threadIdx.x;
    int r = gid >> 7, c = gid & 127;
    float acc = 0.f;
#pragma unroll 8
    for (int k = 0; k < F; k++)
        acc += __ldg(&ew2[r * F + k]) * __ldg(&nw1[k * F + c]);
    g_M[gid] = acc;
}

// ---------------------------------------------------------------------------
// Edge kernel: one warp per edge, fp16 XA/XB reads, fp32 v4 RED scatter.
__global__ void __launch_bounds__(256)
edge_kernel(const void* __restrict__ ei_raw, const float* __restrict__ pos,
            const float* __restrict__ ew1, int E, int N) {
    int gw = (blockIdx.x * blockDim.x + threadIdx.x) >> 5;
    int lane = threadIdx.x & 31;
    if (gw >= E) return;

    int row, col;
    if (g_IS64) {
        const long long* ei = (const long long*)ei_raw;
        row = (int)ei[gw];
        col = (int)ei[(size_t)E + gw];
    } else {
        const int* ei = (const int*)ei_raw;
        row = ei[gw];
        col = ei[E + gw];
    }

    float dx = pos[row * 3 + 0] - pos[col * 3 + 0];
    float dy = pos[row * 3 + 1] - pos[col * 3 + 1];
    float dz = pos[row * 3 + 2] - pos[col * 3 + 2];
    float dist2 = dx * dx + dy * dy + dz * dz;

    // 4 fp16 features per lane = 8 bytes (uint2)
    const uint2* XA2 = (const uint2*)g_XAh;
    const uint2* XB2 = (const uint2*)g_XBh;
    uint2 au = XA2[(size_t)row * 32 + lane];
    uint2 bu = XB2[(size_t)col * 32 + lane];
    float2 a01 = __half22float2(*(const __half2*)&au.x);
    float2 a23 = __half22float2(*(const __half2*)&au.y);
    float2 b01 = __half22float2(*(const __half2*)&bu.x);
    float2 b23 = __half22float2(*(const __half2*)&bu.y);
    float4 w = __ldg((const float4*)(ew1 + 256 * F) + lane);

    float p0 = a01.x + b01.x + dist2 * w.x;
    float p1 = a01.y + b01.y + dist2 * w.y;
    float p2 = a23.x + b23.x + dist2 * w.z;
    float p3 = a23.y + b23.y + dist2 * w.w;

    float s0 = p0 * fast_sigmoid(p0);
    float s1 = p1 * fast_sigmoid(p1);
    float s2 = p2 * fast_sigmoid(p2);
    float s3 = p3 * fast_sigmoid(p3);

    float* aggp = g_AGGS + (size_t)row * F + lane * 4;
    asm volatile("red.global.add.v4.f32 [%0], {%1, %2, %3, %4};"
                 :: "l"(aggp), "f"(s0), "f"(s1), "f"(s2), "f"(s3) : "memory");

    float4 vv = ((const float4*)g_V)[lane];
    float d = s0 * vv.x + s1 * vv.y + s2 * vv.z + s3 * vv.w;
#pragma unroll
    for (int o = 16; o > 0; o >>= 1) d += __shfl_xor_sync(0xffffffffu, d, o);

    if (lane == 0) {
        float sc = fast_tanh(d + g_C0);
        atomicAdd(&g_DELTA[row * 3 + 0], sc * dx);
        atomicAdd(&g_DELTA[row * 3 + 1], sc * dy);
        atomicAdd(&g_DELTA[row * 3 + 2], sc * dz);
        atomicAdd(&g_DEG[row], 1.0f);
    }
}

// ---------------------------------------------------------------------------
// Pipelined register-tiled GEMM. Compile-time: LNFUSE (fused residual+LN),
// HOUT (fp16 output store). <1,0,0> and <0,1,0> are the proven binaries.
#define AS_STRIDE 132
#define WS_BYTES  16384
#define AS_BYTES  16896
#define SM_AS0    (2 * WS_BYTES)
#define SM_RT_TOTAL (2 * WS_BYTES + 2 * AS_BYTES)

template <int ACT, int LNFUSE, int HOUT>
__global__ void __launch_bounds__(256, 2)
gemm_rt(const float* __restrict__ A,
        const float* __restrict__ W0, const float* __restrict__ bias0,
        void* __restrict__ out0,
        const float* __restrict__ W1, const float* __restrict__ bias1,
        void* __restrict__ out1,
        const float* __restrict__ deg, const float* __restrict__ degvec,
        const float* __restrict__ lnx, const float* __restrict__ gamma,
        const float* __restrict__ beta, int N) {
    extern __shared__ char smem[];

    const float* W = W0;
    const float* bias = bias0;
    void* out = out0;
    if (blockIdx.y == 1) { W = W1; bias = bias1; out = out1; }

    int t = threadIdx.x;
    int lane = t & 31, w = t >> 5;
    int txl = lane & 3, tyl = lane >> 2;
    int wx = w & 3, wy = w >> 2;
    int col0 = (wx * 4 + txl) * 8;
    int rowt = (wy * 8 + tyl) * 8;
    int row0 = blockIdx.x * 128;

    uint32_t sb = smem_u32(smem);

    int arl = (w & 3) * 32 + lane;
    int kh  = (w >> 2) * 16;
    int arow = row0 + arl;
    const float4* Abase = (const float4*)(A + (size_t)arow * F);

    int wk = t >> 3, wcol = (t & 7) * 16;

    unsigned long long acc[8][4];
#pragma unroll
    for (int r = 0; r < 8; r++)
#pragma unroll
        for (int c = 0; c < 4; c++) acc[r][c] = 0ull;

    float4 v[4];

    {
        const float* wsrc = W + (size_t)wk * F + wcol;
        uint32_t wdst = sb + (uint32_t)(wk * F + wcol) * 4;
#pragma unroll
        for (int q = 0; q < 4; q++) CP_ASYNC16(wdst + q * 16, wsrc + q * 4);
        CP_COMMIT();
        if (arow < N) {
#pragma unroll
            for (int q = 0; q < 4; q++) v[q] = __ldg(&Abase[(kh >> 2) + q]);
        } else {
#pragma unroll
            for (int q = 0; q < 4; q++) v[q] = make_float4(0.f, 0.f, 0.f, 0.f);
        }
        float* As0 = (float*)(smem + SM_AS0);
#pragma unroll
        for (int q = 0; q < 4; q++) {
            float vals[4] = {v[q].x, v[q].y, v[q].z, v[q].w};
#pragma unroll
            for (int e = 0; e < 4; e++)
                As0[(kh + q * 4 + e) * AS_STRIDE + arl] = vals[e];
        }
        CP_WAIT0();
    }
    __syncthreads();

#pragma unroll 1
    for (int c = 0; c < 4; c++) {
        int cb = c & 1, nb = (c + 1) & 1;
        float* Ws = (float*)(smem + cb * WS_BYTES);
        float* As = (float*)(smem + SM_AS0 + cb * AS_BYTES);

        if (c < 3) {
            const float* wsrc = W + (size_t)((c + 1) * 32 + wk) * F + wcol;
            uint32_t wdst = sb + (uint32_t)nb * WS_BYTES + (uint32_t)(wk * F + wcol) * 4;
#pragma unroll
            for (int q = 0; q < 4; q++) CP_ASYNC16(wdst + q * 16, wsrc + q * 4);
            CP_COMMIT();
            if (arow < N) {
                int kb = ((c + 1) * 32 + kh) >> 2;
#pragma unroll
                for (int q = 0; q < 4; q++) v[q] = __ldg(&Abase[kb + q]);
            }
        }

#pragma unroll
        for (int kk = 0; kk < 32; kk++) {
            float4 al = *(const float4*)&As[kk * AS_STRIDE + rowt];
            float4 ah = *(const float4*)&As[kk * AS_STRIDE + rowt + 4];
            unsigned long long a0 = pack2(al.x), a1 = pack2(al.y);
            unsigned long long a2 = pack2(al.z), a3 = pack2(al.w);
            unsigned long long a4 = pack2(ah.x), a5 = pack2(ah.y);
            unsigned long long a6 = pack2(ah.z), a7 = pack2(ah.w);
            ulonglong2 bv0 = *(const ulonglong2*)&Ws[kk * F + col0];
            ulonglong2 bv1 = *(const ulonglong2*)&Ws[kk * F + col0 + 4];
            FFMA2(acc[0][0], a0, bv0.x); FFMA2(acc[0][1], a0, bv0.y);
            FFMA2(acc[0][2], a0, bv1.x); FFMA2(acc[0][3], a0, bv1.y);
            FFMA2(acc[1][0], a1, bv0.x); FFMA2(acc[1][1], a1, bv0.y);
            FFMA2(acc[1][2], a1, bv1.x); FFMA2(acc[1][3], a1, bv1.y);
            FFMA2(acc[2][0], a2, bv0.x); FFMA2(acc[2][1], a2, bv0.y);
            FFMA2(acc[2][2], a2, bv1.x); FFMA2(acc[2][3], a2, bv1.y);
            FFMA2(acc[3][0], a3, bv0.x); FFMA2(acc[3][1], a3, bv0.y);
            FFMA2(acc[3][2], a3, bv1.x); FFMA2(acc[3][3], a3, bv1.y);
            FFMA2(acc[4][0], a4, bv0.x); FFMA2(acc[4][1], a4, bv0.y);
            FFMA2(acc[4][2], a4, bv1.x); FFMA2(acc[4][3], a4, bv1.y);
            FFMA2(acc[5][0], a5, bv0.x); FFMA2(acc[5][1], a5, bv0.y);
            FFMA2(acc[5][2], a5, bv1.x); FFMA2(acc[5][3], a5, bv1.y);
            FFMA2(acc[6][0], a6, bv0.x); FFMA2(acc[6][1], a6, bv0.y);
            FFMA2(acc[6][2], a6, bv1.x); FFMA2(acc[6][3], a6, bv1.y);
            FFMA2(acc[7][0], a7, bv0.x); FFMA2(acc[7][1], a7, bv0.y);
            FFMA2(acc[7][2], a7, bv1.x); FFMA2(acc[7][3], a7, bv1.y);
        }

        if (c < 3) {
            float* Asn = (float*)(smem + SM_AS0 + nb * AS_BYTES);
            if (arow >= N) {
#pragma unroll
                for (int q = 0; q < 4; q++) v[q] = make_float4(0.f, 0.f, 0.f, 0.f);
            }
#pragma unroll
            for (int q = 0; q < 4; q++) {
                float vals[4] = {v[q].x, v[q].y, v[q].z, v[q].w};
#pragma unroll
                for (int e = 0; e < 4; e++)
                    Asn[(kh + q * 4 + e) * AS_STRIDE + arl] = vals[e];
            }
            CP_WAIT0();
        }
        __syncthreads();
    }

    float bcol[8];
#pragma unroll
    for (int j = 0; j < 8; j++)
        bcol[j] = bias ? __ldg(&bias[col0 + j]) : 0.f;

    if (LNFUSE == 0) {
        float dcol[8];
#pragma unroll
        for (int j = 0; j < 8; j++)
            dcol[j] = degvec ? __ldg(&degvec[col0 + j]) : 0.f;
#pragma unroll
        for (int rr = 0; rr < 8; rr++) {
            int row = row0 + rowt + rr;
            if (row < N) {
                float dg = deg ? deg[row] : 0.f;
                float o[8];
#pragma unroll
                for (int cp = 0; cp < 4; cp++) unpack2(acc[rr][cp], o[2 * cp], o[2 * cp + 1]);
#pragma unroll
                for (int j = 0; j < 8; j++) {
                    float vv2 = o[j] + bcol[j] + dg * dcol[j];
                    if (ACT == 1) vv2 = vv2 * fast_sigmoid(vv2);
                    o[j] = vv2;
                }
                if (HOUT) {
                    __half2 h0 = __floats2half2_rn(o[0], o[1]);
                    __half2 h1 = __floats2half2_rn(o[2], o[3]);
                    __half2 h2 = __floats2half2_rn(o[4], o[5]);
                    __half2 h3 = __floats2half2_rn(o[6], o[7]);
                    uint4 pk = make_uint4(*(uint32_t*)&h0, *(uint32_t*)&h1,
                                          *(uint32_t*)&h2, *(uint32_t*)&h3);
                    *(uint4*)((__half*)out + (size_t)row * F + col0) = pk;
                } else {
                    float4* op = (float4*)((float*)out + (size_t)row * F + col0);
                    op[0] = make_float4(o[0], o[1], o[2], o[3]);
                    op[1] = make_float4(o[4], o[5], o[6], o[7]);
                }
            }
        }
    } else {
        // Fused residual + LayerNorm epilogue.
        float* part = (float*)smem;
        float* smu = (float*)(smem + 16384);
        float* sri = (float*)(smem + 16896);
        int cg = wx * 4 + txl;

#pragma unroll
        for (int rr = 0; rr < 8; rr++) {
            int row = row0 + rowt + rr;
            float s = 0.f, s2 = 0.f;
            if (row < N) {
                float o[8];
#pragma unroll
                for (int cp = 0; cp < 4; cp++) unpack2(acc[rr][cp], o[2 * cp], o[2 * cp + 1]);
                const float4* xp = (const float4*)(lnx + (size_t)row * F + col0);
                float4 x0 = __ldg(&xp[0]), x1 = __ldg(&xp[1]);
                float xv[8] = {x0.x, x0.y, x0.z, x0.w, x1.x, x1.y, x1.z, x1.w};
#pragma unroll
                for (int j = 0; j < 8; j++) {
                    float p = o[j] + bcol[j] + xv[j];
                    s += p;
                    s2 += p * p;
                }
            }
            part[((rowt + rr) * 16 + cg) * 2 + 0] = s;
            part[((rowt + rr) * 16 + cg) * 2 + 1] = s2;
        }
        __syncthreads();

        {
            int row = t >> 1, half = t & 1;
            float s = 0.f, s2 = 0.f;
#pragma unroll
            for (int q = 0; q < 8; q++) {
                s  += part[(row * 16 + half * 8 + q) * 2 + 0];
                s2 += part[(row * 16 + half * 8 + q) * 2 + 1];
            }
            s  += __shfl_xor_sync(0xffffffffu, s, 1);
            s2 += __shfl_xor_sync(0xffffffffu, s2, 1);
            if (half == 0) {
                float mean = s * (1.f / F);
                smu[row] = mean;
                sri[row] = rsqrtf(s2 * (1.f / F) - mean * mean + LN_EPS);
            }
        }
        __syncthreads();

        float gcol[8], becol[8];
#pragma unroll
        for (int j = 0; j < 8; j++) {
            gcol[j]  = __ldg(&gamma[col0 + j]);
            becol[j] = __ldg(&beta[col0 + j]);
        }
#pragma unroll
        for (int rr = 0; rr < 8; rr++) {
            int row = row0 + rowt + rr;
            if (row < N) {
                float mu = smu[rowt + rr];
                float ri = sri[rowt + rr];
                float o[8];
#pragma unroll
                for (int cp = 0; cp < 4; cp++) unpack2(acc[rr][cp], o[2 * cp], o[2 * cp + 1]);
                const float4* xp = (const float4*)(lnx + (size_t)row * F + col0);
                float4 x0 = __ldg(&xp[0]), x1 = __ldg(&xp[1]);
                float xv[8] = {x0.x, x0.y, x0.z, x0.w, x1.x, x1.y, x1.z, x1.w};
#pragma unroll
                for (int j = 0; j < 8; j++) {
                    float p = o[j] + bcol[j] + xv[j];
                    o[j] = gcol[j] * (p - mu) * ri + becol[j];
                }
                float4* op = (float4*)((float*)out + (size_t)row * F + col0);
                op[0] = make_float4(o[0], o[1], o[2], o[3]);
                op[1] = make_float4(o[4], o[5], o[6], o[7]);
            }
        }
    }
}

// ---------------------------------------------------------------------------
__global__ void pos_kernel(const float* __restrict__ pos, float* __restrict__ out, int N) {
    int i = blockIdx.x * blockDim.x + threadIdx.x;
    if (i < N * 3) out[i] = pos[i] + g_DELTA[i];
}

// ---------------------------------------------------------------------------
extern "C" void kernel_launch(void* const* d_in, const int* in_sizes, int n_in,
                              void* d_out, int out_size) {
    const float* x     = (const float*)d_in[0];
    const float* pos   = (const float*)d_in[1];
    const void*  ei    = d_in[2];
    const float* ew1   = (const float*)d_in[3];
    const float* eb1   = (const float*)d_in[4];
    const float* ew2   = (const float*)d_in[5];
    const float* eb2   = (const float*)d_in[6];
    const float* nw1   = (const float*)d_in[7];
    const float* nb1   = (const float*)d_in[8];
    const float* nw2   = (const float*)d_in[9];
    const float* nb2   = (const float*)d_in[10];
    const float* cw    = (const float*)d_in[11];
    const float* cb    = (const float*)d_in[12];
    const float* gamma = (const float*)d_in[13];
    const float* beta  = (const float*)d_in[14];

    int N = in_sizes[0] / F;
    int E = in_sizes[2] / 2;

    float* xout = (float*)d_out;
    float* pout = (float*)d_out + (size_t)N * F;

    __half* XAh; cudaGetSymbolAddress((void**)&XAh, g_XAh);
    __half* XBh; cudaGetSymbolAddress((void**)&XBh, g_XBh);
    float* XB;   cudaGetSymbolAddress((void**)&XB,   g_XB);
    float* AGGS; cudaGetSymbolAddress((void**)&AGGS, g_AGGS);
    float* DELTA; cudaGetSymbolAddress((void**)&DELTA, g_DELTA);
    float* DEG;  cudaGetSymbolAddress((void**)&DEG,  g_DEG);
    float* VD;   cudaGetSymbolAddress((void**)&VD,   g_VD);
    float* M;    cudaGetSymbolAddress((void**)&M,    g_M);

    cudaFuncSetAttribute(gemm_rt<0, 0, 1>, cudaFuncAttributeMaxDynamicSharedMemorySize, SM_RT_TOTAL);
    cudaFuncSetAttribute(gemm_rt<1, 0, 0>, cudaFuncAttributeMaxDynamicSharedMemorySize, SM_RT_TOTAL);
    cudaFuncSetAttribute(gemm_rt<0, 1, 0>, cudaFuncAttributeMaxDynamicSharedMemorySize, SM_RT_TOTAL);

    int tcb = (N + 127) / 128;

    detect_kernel<<<1, 256>>>(ei, E, N);
    prep_vc<<<1, 128>>>(ew2, cw, eb2, cb, nw1);
    prep_m<<<64, 256>>>(ew2, nw1);

    // Zero accumulators via graph-capturable async memsets
    cudaMemsetAsync(AGGS, 0, (size_t)N * F * sizeof(float));
    cudaMemsetAsync(DELTA, 0, (size_t)N * 3 * sizeof(float));
    cudaMemsetAsync(DEG, 0, (size_t)N * sizeof(float));

    // XAh = fp16(x @ W1a + eb1) AND XBh = fp16(x @ W1b) — merged dual launch
    gemm_rt<0, 0, 1><<<dim3(tcb, 2), 256, SM_RT_TOTAL>>>(
        x, ew1, eb1, XAh, ew1 + 128 * F, nullptr, XBh,
        nullptr, nullptr, nullptr, nullptr, nullptr, N);

    // Edge stage (fp16 feature reads, fp32 accumulate)
    int eblocks = (E * 32 + 255) / 256;
    edge_kernel<<<eblocks, 256>>>(ei, pos, ew1, E, N);

    // H = silu(AGGS @ M + deg*VD + nb1) -> XB
    gemm_rt<1, 0, 0><<<tcb, 256, SM_RT_TOTAL>>>(AGGS, M, nb1, XB,
                                                nullptr, nullptr, nullptr,
                                                DEG, VD, nullptr, nullptr, nullptr, N);
    // x_out = LN(x + H @ nw2 + nb2) — fused instantiation
    gemm_rt<0, 1, 0><<<tcb, 256, SM_RT_TOTAL>>>(XB, nw2, nb2, xout,
                                                nullptr, nullptr, nullptr,
                                                nullptr, nullptr, x, gamma, beta, N);
    // pos_out
    pos_kernel<<<(N * 3 + 255) / 256, 256>>>(pos, pout, N);
}

// round 17
// speedup vs baseline: 1.4435x; 1.0748x over previous
#include <cuda_runtime.h>
#include <cuda_bf16.h>
#include <cuda_fp16.h>
#include <math.h>
#include <stdint.h>

#define NMAX 50048
#define F 128
#define LN_EPS 1e-5f

// ---------------------------------------------------------------------------
// Scratch (device globals — no allocation allowed)
__device__ __half g_XAh[NMAX * F];   // fp16 x@W1a+eb1 (edge-kernel feed)
__device__ __half g_XBh[NMAX * F];   // fp16 x@W1b
__device__ float g_XB[NMAX * F];     // fp32 H (node MLP hidden)
__device__ float g_AGGS[NMAX * F];
__device__ float g_DELTA[NMAX * 3];
__device__ float g_DEG[NMAX];
__device__ float g_V[F];
__device__ float g_VD[F];            // eb2 @ nw1
__device__ float g_M[F * F];         // ew2 @ nw1
__device__ float g_C0;
__device__ int   g_IS64;

// ---------------------------------------------------------------------------
#define FFMA2(acc, a, b) \
    asm("fma.rn.f32x2 %0, %1, %2, %0;" : "+l"(acc) : "l"(a), "l"(b))
__device__ __forceinline__ unsigned long long pack2(float v) {
    unsigned long long r;
    unsigned int u = __float_as_uint(v);
    asm("mov.b64 %0, {%1, %1};" : "=l"(r) : "r"(u));
    return r;
}
__device__ __forceinline__ void unpack2(unsigned long long p, float& lo, float& hi) {
    unsigned int a, b;
    asm("mov.b64 {%0, %1}, %2;" : "=r"(a), "=r"(b) : "l"(p));
    lo = __uint_as_float(a);
    hi = __uint_as_float(b);
}
__device__ __forceinline__ uint32_t smem_u32(const void* p) {
    uint32_t a;
    asm("{ .reg .u64 t; cvta.to.shared.u64 t, %1; cvt.u32.u64 %0, t; }"
        : "=r"(a) : "l"(p));
    return a;
}
#define CP_ASYNC16(dst, src) \
    asm volatile("cp.async.cg.shared.global [%0], [%1], 16;" :: "r"(dst), "l"(src))
#define CP_COMMIT() asm volatile("cp.async.commit_group;" ::: "memory")
#define CP_WAIT0()  asm volatile("cp.async.wait_group 0;" ::: "memory")

__device__ __forceinline__ float fast_sigmoid(float p) {
    return __fdividef(1.f, 1.f + __expf(-p));
}
__device__ __forceinline__ float fast_tanh(float x) {
    return 1.f - __fdividef(2.f, __expf(2.f * x) + 1.f);
}

// ---------------------------------------------------------------------------
__global__ void detect_kernel(const void* ei, int E, int N) {
    __shared__ int bad;
    if (threadIdx.x == 0) bad = 0;
    __syncthreads();
    int cnt = (2 * E < 256) ? 2 * E : 256;
    if ((int)threadIdx.x < cnt) {
        long long v = ((const long long*)ei)[threadIdx.x];
        if (v < 0 || v >= N) bad = 1;
    }
    __syncthreads();
    if (threadIdx.x == 0) g_IS64 = !bad;
}

// V = ew2 @ cw, C0 = eb2.cw + cb, VD = eb2 @ nw1
__global__ void prep_vc(const float* __restrict__ ew2, const float* __restrict__ cw,
                        const float* __restrict__ eb2, const float* __restrict__ cb,
                        const float* __restrict__ nw1) {
    int t = threadIdx.x;
    float s = 0.f;
    for (int o = 0; o < F; o++) s += ew2[t * F + o] * cw[o];
    g_V[t] = s;
    float vd = 0.f;
    for (int j = 0; j < F; j++) vd += eb2[j] * nw1[j * F + t];
    g_VD[t] = vd;
    if (t == 0) {
        float c = cb[0];
        for (int o = 0; o < F; o++) c += eb2[o] * cw[o];
        g_C0 = c;
    }
}

// Parallel M = ew2 @ nw1
__global__ void __launch_bounds__(256)
prep_m(const float* __restrict__ ew2, const float* __restrict__ nw1) {
    int gid = blockIdx.x * 256 + threadIdx.x;
    int r = gid >> 7, c = gid & 127;
    float acc = 0.f;
#pragma unroll 8
    for (int k = 0; k < F; k++)
        acc += __ldg(&ew2[r * F + k]) * __ldg(&nw1[k * F + c]);
    g_M[gid] = acc;
}

// ---------------------------------------------------------------------------
// Edge kernel: TWO edges per warp, fully interleaved for latency hiding.
// fp16 XA/XB reads, fp32 v4 RED scatter.
__global__ void __launch_bounds__(256)
edge_kernel(const void* __restrict__ ei_raw, const float* __restrict__ pos,
            const float* __restrict__ ew1, int E, int N) {
    int gw = (blockIdx.x * blockDim.x + threadIdx.x) >> 5;
    int lane = threadIdx.x & 31;
    int e0 = gw * 2;
    if (e0 >= E) return;
    int e1 = e0 + 1;
    bool has1 = (e1 < E);

    int row0, col0, row1 = 0, col1 = 0;
    if (g_IS64) {
        const long long* ei = (const long long*)ei_raw;
        row0 = (int)ei[e0];
        col0 = (int)ei[(size_t)E + e0];
        if (has1) { row1 = (int)ei[e1]; col1 = (int)ei[(size_t)E + e1]; }
    } else {
        const int* ei = (const int*)ei_raw;
        row0 = ei[e0];
        col0 = ei[E + e0];
        if (has1) { row1 = ei[e1]; col1 = ei[E + e1]; }
    }
    if (!has1) { row1 = row0; col1 = col0; }   // dummy (masked at writeback)

    // Position diffs (broadcast loads)
    float dx0 = pos[row0 * 3 + 0] - pos[col0 * 3 + 0];
    float dy0 = pos[row0 * 3 + 1] - pos[col0 * 3 + 1];
    float dz0 = pos[row0 * 3 + 2] - pos[col0 * 3 + 2];
    float dx1 = pos[row1 * 3 + 0] - pos[col1 * 3 + 0];
    float dy1 = pos[row1 * 3 + 1] - pos[col1 * 3 + 1];
    float dz1 = pos[row1 * 3 + 2] - pos[col1 * 3 + 2];
    float d20 = dx0 * dx0 + dy0 * dy0 + dz0 * dz0;
    float d21 = dx1 * dx1 + dy1 * dy1 + dz1 * dz1;

    // Feature gathers — both edges issued back-to-back (ILP 4 loads)
    const uint2* XA2 = (const uint2*)g_XAh;
    const uint2* XB2 = (const uint2*)g_XBh;
    uint2 au0 = XA2[(size_t)row0 * 32 + lane];
    uint2 bu0 = XB2[(size_t)col0 * 32 + lane];
    uint2 au1 = XA2[(size_t)row1 * 32 + lane];
    uint2 bu1 = XB2[(size_t)col1 * 32 + lane];
    float4 w = __ldg((const float4*)(ew1 + 256 * F) + lane);
    float4 vv = ((const float4*)g_V)[lane];

    float2 a001 = __half22float2(*(const __half2*)&au0.x);
    float2 a023 = __half22float2(*(const __half2*)&au0.y);
    float2 b001 = __half22float2(*(const __half2*)&bu0.x);
    float2 b023 = __half22float2(*(const __half2*)&bu0.y);
    float2 a101 = __half22float2(*(const __half2*)&au1.x);
    float2 a123 = __half22float2(*(const __half2*)&au1.y);
    float2 b101 = __half22float2(*(const __half2*)&bu1.x);
    float2 b123 = __half22float2(*(const __half2*)&bu1.y);

    float p00 = a001.x + b001.x + d20 * w.x;
    float p01 = a001.y + b001.y + d20 * w.y;
    float p02 = a023.x + b023.x + d20 * w.z;
    float p03 = a023.y + b023.y + d20 * w.w;
    float p10 = a101.x + b101.x + d21 * w.x;
    float p11 = a101.y + b101.y + d21 * w.y;
    float p12 = a123.x + b123.x + d21 * w.z;
    float p13 = a123.y + b123.y + d21 * w.w;

    float s00 = p00 * fast_sigmoid(p00);
    float s01 = p01 * fast_sigmoid(p01);
    float s02 = p02 * fast_sigmoid(p02);
    float s03 = p03 * fast_sigmoid(p03);
    float s10 = p10 * fast_sigmoid(p10);
    float s11 = p11 * fast_sigmoid(p11);
    float s12 = p12 * fast_sigmoid(p12);
    float s13 = p13 * fast_sigmoid(p13);

    // Scatter edge 0 (always), edge 1 (if valid)
    {
        float* aggp = g_AGGS + (size_t)row0 * F + lane * 4;
        asm volatile("red.global.add.v4.f32 [%0], {%1, %2, %3, %4};"
                     :: "l"(aggp), "f"(s00), "f"(s01), "f"(s02), "f"(s03) : "memory");
    }
    if (has1) {
        float* aggp = g_AGGS + (size_t)row1 * F + lane * 4;
        asm volatile("red.global.add.v4.f32 [%0], {%1, %2, %3, %4};"
                     :: "l"(aggp), "f"(s10), "f"(s11), "f"(s12), "f"(s13) : "memory");
    }

    // Dual interleaved butterflies
    float d0 = s00 * vv.x + s01 * vv.y + s02 * vv.z + s03 * vv.w;
    float d1 = s10 * vv.x + s11 * vv.y + s12 * vv.z + s13 * vv.w;
#pragma unroll
    for (int o = 16; o > 0; o >>= 1) {
        d0 += __shfl_xor_sync(0xffffffffu, d0, o);
        d1 += __shfl_xor_sync(0xffffffffu, d1, o);
    }

    if (lane == 0) {
        float c0 = g_C0;
        float sc0 = fast_tanh(d0 + c0);
        atomicAdd(&g_DELTA[row0 * 3 + 0], sc0 * dx0);
        atomicAdd(&g_DELTA[row0 * 3 + 1], sc0 * dy0);
        atomicAdd(&g_DELTA[row0 * 3 + 2], sc0 * dz0);
        atomicAdd(&g_DEG[row0], 1.0f);
        if (has1) {
            float sc1 = fast_tanh(d1 + c0);
            atomicAdd(&g_DELTA[row1 * 3 + 0], sc1 * dx1);
            atomicAdd(&g_DELTA[row1 * 3 + 1], sc1 * dy1);
            atomicAdd(&g_DELTA[row1 * 3 + 2], sc1 * dz1);
            atomicAdd(&g_DEG[row1], 1.0f);
        }
    }
}

// ---------------------------------------------------------------------------
// Pipelined register-tiled GEMM. Compile-time: LNFUSE (fused residual+LN),
// HOUT (fp16 output store).
#define AS_STRIDE 132
#define WS_BYTES  16384
#define AS_BYTES  16896
#define SM_AS0    (2 * WS_BYTES)
#define SM_RT_TOTAL (2 * WS_BYTES + 2 * AS_BYTES)

template <int ACT, int LNFUSE, int HOUT>
__global__ void __launch_bounds__(256, 2)
gemm_rt(const float* __restrict__ A,
        const float* __restrict__ W0, const float* __restrict__ bias0,
        void* __restrict__ out0,
        const float* __restrict__ W1, const float* __restrict__ bias1,
        void* __restrict__ out1,
        const float* __restrict__ deg, const float* __restrict__ degvec,
        const float* __restrict__ lnx, const float* __restrict__ gamma,
        const float* __restrict__ beta, int N) {
    extern __shared__ char smem[];

    const float* W = W0;
    const float* bias = bias0;
    void* out = out0;
    if (blockIdx.y == 1) { W = W1; bias = bias1; out = out1; }

    int t = threadIdx.x;
    int lane = t & 31, w = t >> 5;
    int txl = lane & 3, tyl = lane >> 2;
    int wx = w & 3, wy = w >> 2;
    int col0 = (wx * 4 + txl) * 8;
    int rowt = (wy * 8 + tyl) * 8;
    int row0 = blockIdx.x * 128;

    uint32_t sb = smem_u32(smem);

    int arl = (w & 3) * 32 + lane;
    int kh  = (w >> 2) * 16;
    int arow = row0 + arl;
    const float4* Abase = (const float4*)(A + (size_t)arow * F);

    int wk = t >> 3, wcol = (t & 7) * 16;

    unsigned long long acc[8][4];
#pragma unroll
    for (int r = 0; r < 8; r++)
#pragma unroll
        for (int c = 0; c < 4; c++) acc[r][c] = 0ull;

    float4 v[4];

    {
        const float* wsrc = W + (size_t)wk * F + wcol;
        uint32_t wdst = sb + (uint32_t)(wk * F + wcol) * 4;
#pragma unroll
        for (int q = 0; q < 4; q++) CP_ASYNC16(wdst + q * 16, wsrc + q * 4);
        CP_COMMIT();
        if (arow < N) {
#pragma unroll
            for (int q = 0; q < 4; q++) v[q] = __ldg(&Abase[(kh >> 2) + q]);
        } else {
#pragma unroll
            for (int q = 0; q < 4; q++) v[q] = make_float4(0.f, 0.f, 0.f, 0.f);
        }
        float* As0 = (float*)(smem + SM_AS0);
#pragma unroll
        for (int q = 0; q < 4; q++) {
            float vals[4] = {v[q].x, v[q].y, v[q].z, v[q].w};
#pragma unroll
            for (int e = 0; e < 4; e++)
                As0[(kh + q * 4 + e) * AS_STRIDE + arl] = vals[e];
        }
        CP_WAIT0();
    }
    __syncthreads();

#pragma unroll 1
    for (int c = 0; c < 4; c++) {
        int cb = c & 1, nb = (c + 1) & 1;
        float* Ws = (float*)(smem + cb * WS_BYTES);
        float* As = (float*)(smem + SM_AS0 + cb * AS_BYTES);

        if (c < 3) {
            const float* wsrc = W + (size_t)((c + 1) * 32 + wk) * F + wcol;
            uint32_t wdst = sb + (uint32_t)nb * WS_BYTES + (uint32_t)(wk * F + wcol) * 4;
#pragma unroll
            for (int q = 0; q < 4; q++) CP_ASYNC16(wdst + q * 16, wsrc + q * 4);
            CP_COMMIT();
            if (arow < N) {
                int kb = ((c + 1) * 32 + kh) >> 2;
#pragma unroll
                for (int q = 0; q < 4; q++) v[q] = __ldg(&Abase[kb + q]);
            }
        }

#pragma unroll
        for (int kk = 0; kk < 32; kk++) {
            float4 al = *(const float4*)&As[kk * AS_STRIDE + rowt];
            float4 ah = *(const float4*)&As[kk * AS_STRIDE + rowt + 4];
            unsigned long long a0 = pack2(al.x), a1 = pack2(al.y);
            unsigned long long a2 = pack2(al.z), a3 = pack2(al.w);
            unsigned long long a4 = pack2(ah.x), a5 = pack2(ah.y);
            unsigned long long a6 = pack2(ah.z), a7 = pack2(ah.w);
            ulonglong2 bv0 = *(const ulonglong2*)&Ws[kk * F + col0];
            ulonglong2 bv1 = *(const ulonglong2*)&Ws[kk * F + col0 + 4];
            FFMA2(acc[0][0], a0, bv0.x); FFMA2(acc[0][1], a0, bv0.y);
            FFMA2(acc[0][2], a0, bv1.x); FFMA2(acc[0][3], a0, bv1.y);
            FFMA2(acc[1][0], a1, bv0.x); FFMA2(acc[1][1], a1, bv0.y);
            FFMA2(acc[1][2], a1, bv1.x); FFMA2(acc[1][3], a1, bv1.y);
            FFMA2(acc[2][0], a2, bv0.x); FFMA2(acc[2][1], a2, bv0.y);
            FFMA2(acc[2][2], a2, bv1.x); FFMA2(acc[2][3], a2, bv1.y);
            FFMA2(acc[3][0], a3, bv0.x); FFMA2(acc[3][1], a3, bv0.y);
            FFMA2(acc[3][2], a3, bv1.x); FFMA2(acc[3][3], a3, bv1.y);
            FFMA2(acc[4][0], a4, bv0.x); FFMA2(acc[4][1], a4, bv0.y);
            FFMA2(acc[4][2], a4, bv1.x); FFMA2(acc[4][3], a4, bv1.y);
            FFMA2(acc[5][0], a5, bv0.x); FFMA2(acc[5][1], a5, bv0.y);
            FFMA2(acc[5][2], a5, bv1.x); FFMA2(acc[5][3], a5, bv1.y);
            FFMA2(acc[6][0], a6, bv0.x); FFMA2(acc[6][1], a6, bv0.y);
            FFMA2(acc[6][2], a6, bv1.x); FFMA2(acc[6][3], a6, bv1.y);
            FFMA2(acc[7][0], a7, bv0.x); FFMA2(acc[7][1], a7, bv0.y);
            FFMA2(acc[7][2], a7, bv1.x); FFMA2(acc[7][3], a7, bv1.y);
        }

        if (c < 3) {
            float* Asn = (float*)(smem + SM_AS0 + nb * AS_BYTES);
            if (arow >= N) {
#pragma unroll
                for (int q = 0; q < 4; q++) v[q] = make_float4(0.f, 0.f, 0.f, 0.f);
            }
#pragma unroll
            for (int q = 0; q < 4; q++) {
                float vals[4] = {v[q].x, v[q].y, v[q].z, v[q].w};
#pragma unroll
                for (int e = 0; e < 4; e++)
                    Asn[(kh + q * 4 + e) * AS_STRIDE + arl] = vals[e];
            }
            CP_WAIT0();
        }
        __syncthreads();
    }

    float bcol[8];
#pragma unroll
    for (int j = 0; j < 8; j++)
        bcol[j] = bias ? __ldg(&bias[col0 + j]) : 0.f;

    if (LNFUSE == 0) {
        float dcol[8];
#pragma unroll
        for (int j = 0; j < 8; j++)
            dcol[j] = degvec ? __ldg(&degvec[col0 + j]) : 0.f;
#pragma unroll
        for (int rr = 0; rr < 8; rr++) {
            int row = row0 + rowt + rr;
            if (row < N) {
                float dg = deg ? deg[row] : 0.f;
                float o[8];
#pragma unroll
                for (int cp = 0; cp < 4; cp++) unpack2(acc[rr][cp], o[2 * cp], o[2 * cp + 1]);
#pragma unroll
                for (int j = 0; j < 8; j++) {
                    float vv2 = o[j] + bcol[j] + dg * dcol[j];
                    if (ACT == 1) vv2 = vv2 * fast_sigmoid(vv2);
                    o[j] = vv2;
                }
                if (HOUT) {
                    __half2 h0 = __floats2half2_rn(o[0], o[1]);
                    __half2 h1 = __floats2half2_rn(o[2], o[3]);
                    __half2 h2 = __floats2half2_rn(o[4], o[5]);
                    __half2 h3 = __floats2half2_rn(o[6], o[7]);
                    uint4 pk = make_uint4(*(uint32_t*)&h0, *(uint32_t*)&h1,
                                          *(uint32_t*)&h2, *(uint32_t*)&h3);
                    *(uint4*)((__half*)out + (size_t)row * F + col0) = pk;
                } else {
                    float4* op = (float4*)((float*)out + (size_t)row * F + col0);
                    op[0] = make_float4(o[0], o[1], o[2], o[3]);
                    op[1] = make_float4(o[4], o[5], o[6], o[7]);
                }
            }
        }
    } else {
        // Fused residual + LayerNorm epilogue.
        float* part = (float*)smem;
        float* smu = (float*)(smem + 16384);
        float* sri = (float*)(smem + 16896);
        int cg = wx * 4 + txl;

#pragma unroll
        for (int rr = 0; rr < 8; rr++) {
            int row = row0 + rowt + rr;
            float s = 0.f, s2 = 0.f;
            if (row < N) {
                float o[8];
#pragma unroll
                for (int cp = 0; cp < 4; cp++) unpack2(acc[rr][cp], o[2 * cp], o[2 * cp + 1]);
                const float4* xp = (const float4*)(lnx + (size_t)row * F + col0);
                float4 x0 = __ldg(&xp[0]), x1 = __ldg(&xp[1]);
                float xv[8] = {x0.x, x0.y, x0.z, x0.w, x1.x, x1.y, x1.z, x1.w};
#pragma unroll
                for (int j = 0; j < 8; j++) {
                    float p = o[j] + bcol[j] + xv[j];
                    s += p;
                    s2 += p * p;
                }
            }
            part[((rowt + rr) * 16 + cg) * 2 + 0] = s;
            part[((rowt + rr) * 16 + cg) * 2 + 1] = s2;
        }
        __syncthreads();

        {
            int row = t >> 1, half = t & 1;
            float s = 0.f, s2 = 0.f;
#pragma unroll
            for (int q = 0; q < 8; q++) {
                s  += part[(row * 16 + half * 8 + q) * 2 + 0];
                s2 += part[(row * 16 + half * 8 + q) * 2 + 1];
            }
            s  += __shfl_xor_sync(0xffffffffu, s, 1);
            s2 += __shfl_xor_sync(0xffffffffu, s2, 1);
            if (half == 0) {
                float mean = s * (1.f / F);
                smu[row] = mean;
                sri[row] = rsqrtf(s2 * (1.f / F) - mean * mean + LN_EPS);
            }
        }
        __syncthreads();

        float gcol[8], becol[8];
#pragma unroll
        for (int j = 0; j < 8; j++) {
            gcol[j]  = __ldg(&gamma[col0 + j]);
            becol[j] = __ldg(&beta[col0 + j]);
        }
#pragma unroll
        for (int rr = 0; rr < 8; rr++) {
            int row = row0 + rowt + rr;
            if (row < N) {
                float mu = smu[rowt + rr];
                float ri = sri[rowt + rr];
                float o[8];
#pragma unroll
                for (int cp = 0; cp < 4; cp++) unpack2(acc[rr][cp], o[2 * cp], o[2 * cp + 1]);
                const float4* xp = (const float4*)(lnx + (size_t)row * F + col0);
                float4 x0 = __ldg(&xp[0]), x1 = __ldg(&xp[1]);
                float xv[8] = {x0.x, x0.y, x0.z, x0.w, x1.x, x1.y, x1.z, x1.w};
#pragma unroll
                for (int j = 0; j < 8; j++) {
                    float p = o[j] + bcol[j] + xv[j];
                    o[j] = gcol[j] * (p - mu) * ri + becol[j];
                }
                float4* op = (float4*)((float*)out + (size_t)row * F + col0);
                op[0] = make_float4(o[0], o[1], o[2], o[3]);
                op[1] = make_float4(o[4], o[5], o[6], o[7]);
            }
        }
    }
}

// ---------------------------------------------------------------------------
__global__ void pos_kernel(const float* __restrict__ pos, float* __restrict__ out, int N) {
    int i = blockIdx.x * blockDim.x + threadIdx.x;
    if (i < N * 3) out[i] = pos[i] + g_DELTA[i];
}

// ---------------------------------------------------------------------------
extern "C" void kernel_launch(void* const* d_in, const int* in_sizes, int n_in,
                              void* d_out, int out_size) {
    const float* x     = (const float*)d_in[0];
    const float* pos   = (const float*)d_in[1];
    const void*  ei    = d_in[2];
    const float* ew1   = (const float*)d_in[3];
    const float* eb1   = (const float*)d_in[4];
    const float* ew2   = (const float*)d_in[5];
    const float* eb2   = (const float*)d_in[6];
    const float* nw1   = (const float*)d_in[7];
    const float* nb1   = (const float*)d_in[8];
    const float* nw2   = (const float*)d_in[9];
    const float* nb2   = (const float*)d_in[10];
    const float* cw    = (const float*)d_in[11];
    const float* cb    = (const float*)d_in[12];
    const float* gamma = (const float*)d_in[13];
    const float* beta  = (const float*)d_in[14];

    int N = in_sizes[0] / F;
    int E = in_sizes[2] / 2;

    float* xout = (float*)d_out;
    float* pout = (float*)d_out + (size_t)N * F;

    __half* XAh; cudaGetSymbolAddress((void**)&XAh, g_XAh);
    __half* XBh; cudaGetSymbolAddress((void**)&XBh, g_XBh);
    float* XB;   cudaGetSymbolAddress((void**)&XB,   g_XB);
    float* AGGS; cudaGetSymbolAddress((void**)&AGGS, g_AGGS);
    float* DELTA; cudaGetSymbolAddress((void**)&DELTA, g_DELTA);
    float* DEG;  cudaGetSymbolAddress((void**)&DEG,  g_DEG);
    float* VD;   cudaGetSymbolAddress((void**)&VD,   g_VD);
    float* M;    cudaGetSymbolAddress((void**)&M,    g_M);

    cudaFuncSetAttribute(gemm_rt<0, 0, 1>, cudaFuncAttributeMaxDynamicSharedMemorySize, SM_RT_TOTAL);
    cudaFuncSetAttribute(gemm_rt<1, 0, 0>, cudaFuncAttributeMaxDynamicSharedMemorySize, SM_RT_TOTAL);
    cudaFuncSetAttribute(gemm_rt<0, 1, 0>, cudaFuncAttributeMaxDynamicSharedMemorySize, SM_RT_TOTAL);

    int tcb = (N + 127) / 128;

    detect_kernel<<<1, 256>>>(ei, E, N);
    prep_vc<<<1, 128>>>(ew2, cw, eb2, cb, nw1);
    prep_m<<<64, 256>>>(ew2, nw1);

    // Zero accumulators via graph-capturable async memsets
    cudaMemsetAsync(AGGS, 0, (size_t)N * F * sizeof(float));
    cudaMemsetAsync(DELTA, 0, (size_t)N * 3 * sizeof(float));
    cudaMemsetAsync(DEG, 0, (size_t)N * sizeof(float));

    // XAh = fp16(x @ W1a + eb1) AND XBh = fp16(x @ W1b) — merged dual launch
    gemm_rt<0, 0, 1><<<dim3(tcb, 2), 256, SM_RT_TOTAL>>>(
        x, ew1, eb1, XAh, ew1 + 128 * F, nullptr, XBh,
        nullptr, nullptr, nullptr, nullptr, nullptr, N);

    // Edge stage: 2 edges per warp
    int nwarps = (E + 1) / 2;
    int eblocks = (nwarps * 32 + 255) / 256;
    edge_kernel<<<eblocks, 256>>>(ei, pos, ew1, E, N);

    // H = silu(AGGS @ M + deg*VD + nb1) -> XB
    gemm_rt<1, 0, 0><<<tcb, 256, SM_RT_TOTAL>>>(AGGS, M, nb1, XB,
                                                nullptr, nullptr, nullptr,
                                                DEG, VD, nullptr, nullptr, nullptr, N);
    // x_out = LN(x + H @ nw2 + nb2) — fused instantiation
    gemm_rt<0, 1, 0><<<tcb, 256, SM_RT_TOTAL>>>(XB, nw2, nb2, xout,
                                                nullptr, nullptr, nullptr,
                                                nullptr, nullptr, x, gamma, beta, N);
    // pos_out
    pos_kernel<<<(N * 3 + 255) / 256, 256>>>(pos, pout, N);
}